// round 6
// baseline (speedup 1.0000x reference)
#include <cuda_runtime.h>
#include <cuda_bf16.h>

// Problem constants: B=8, C=64, H=W=128, G=2, D=32, K=9, OS=2.0
#define PB 16384
#define NB 8
#define NROWS (NB * PB)

__device__ float g_value[NB * PB * 64];   // (b,p,64)
__device__ float g_om[NB * PB * 54];      // (b,p,54)

// XOR swizzle: rows stride 64 floats, swizzle k by row to decollide banks.
#define SW(r) (((r) & 7) << 2)

__device__ __forceinline__ unsigned f2tf(float f) {
    unsigned r; asm("cvt.rna.tf32.f32 %0, %1;" : "=r"(r) : "f"(f)); return r;
}
__device__ __forceinline__ void split_tf(float f, unsigned& hi, unsigned& lo) {
    hi = f2tf(f);
    lo = f2tf(f - __uint_as_float(hi));
}
__device__ __forceinline__ void mma8(float* c, unsigned a0, unsigned a1,
                                     unsigned a2, unsigned a3,
                                     unsigned b0, unsigned b1) {
    asm("mma.sync.aligned.m16n8k8.row.col.f32.tf32.tf32.f32 "
        "{%0,%1,%2,%3},{%4,%5,%6,%7},{%8,%9},{%0,%1,%2,%3};"
        : "+f"(c[0]), "+f"(c[1]), "+f"(c[2]), "+f"(c[3])
        : "r"(a0), "r"(a1), "r"(a2), "r"(a3), "r"(b0), "r"(b1));
}

// ---------------------------------------------------------------------------
// K1: value projection via 3xTF32 mma. 64 rows/block, A staged in swizzled
// smem (coalesced float4 global loads). Warp = (m-tile 0..3, nt-half 0..1).
// smem: Bh 16K + Bl 16K + As 16K = 48KB.
// ---------------------------------------------------------------------------
__global__ void __launch_bounds__(256) k1_valproj(const float* __restrict__ x,
                                                  const float* __restrict__ vp_w,
                                                  const float* __restrict__ vp_b) {
    __shared__ unsigned Bh[4096], Bl[4096];   // [n][k] swizzled
    __shared__ float As[4096];                // [r][k] swizzled (64x64)
    int t = threadIdx.x;
    for (int i = t; i < 4096; i += 256) {
        int n = i >> 6, k = i & 63;
        unsigned h, l; split_tf(vp_w[i], h, l);
        int idx = n * 64 + (k ^ SW(n));
        Bh[idx] = h; Bl[idx] = l;
    }
    size_t row0 = (size_t)blockIdx.x * 64;
    const float4* xv = (const float4*)(x + row0 * 64);
    for (int i = t; i < 1024; i += 256) {
        int r = i >> 4, c4 = (i & 15) * 4;
        *(float4*)&As[r * 64 + (c4 ^ SW(r))] = xv[i];
    }
    __syncthreads();

    int w = t >> 5, lane = t & 31;
    int r = lane >> 2, q = lane & 3;
    int mt = w & 3;            // m-tile (16 rows)
    int nth = w >> 2;          // nt half: nt = nth*4 + 0..3
    int rA = mt * 16 + r;
    int rB = rA + 8;
    int sA_ = SW(rA), sB_ = SW(rB);

    float acc[4][4];
#pragma unroll
    for (int nt = 0; nt < 4; nt++)
#pragma unroll
        for (int i = 0; i < 4; i++) acc[nt][i] = 0.f;

#pragma unroll
    for (int kc = 0; kc < 8; kc++) {
        int k = kc * 8 + q;
        float a0f = As[rA * 64 + (k ^ sA_)];
        float a1f = As[rB * 64 + (k ^ sB_)];
        float a2f = As[rA * 64 + ((k + 4) ^ sA_)];
        float a3f = As[rB * 64 + ((k + 4) ^ sB_)];
        unsigned ah0, ah1, ah2, ah3, al0, al1, al2, al3;
        split_tf(a0f, ah0, al0); split_tf(a1f, ah1, al1);
        split_tf(a2f, ah2, al2); split_tf(a3f, ah3, al3);
#pragma unroll
        for (int nt = 0; nt < 4; nt++) {
            int n0 = (nth * 4 + nt) * 8 + r;
            int base = n0 * 64, s = SW(n0);
            unsigned bh0 = Bh[base + (k ^ s)];
            unsigned bh1 = Bh[base + ((k + 4) ^ s)];
            unsigned bl0 = Bl[base + (k ^ s)];
            unsigned bl1 = Bl[base + ((k + 4) ^ s)];
            mma8(acc[nt], ah0, ah1, ah2, ah3, bh0, bh1);
            mma8(acc[nt], ah0, ah1, ah2, ah3, bl0, bl1);
            mma8(acc[nt], al0, al1, al2, al3, bh0, bh1);
        }
    }
#pragma unroll
    for (int nt = 0; nt < 4; nt++) {
        int jc = (nth * 4 + nt) * 8 + 2 * q;
        float2 b2 = __ldg((const float2*)(vp_b + jc));
        *(float2*)&g_value[(row0 + rA) * 64 + jc] =
            make_float2(acc[nt][0] + b2.x, acc[nt][1] + b2.y);
        *(float2*)&g_value[(row0 + rB) * 64 + jc] =
            make_float2(acc[nt][2] + b2.x, acc[nt][3] + b2.y);
    }
}

// ---------------------------------------------------------------------------
// K2: depthwise 3x3 conv (sliding window) + om GEMM via 3xTF32 mma.
// (round-4 version, unchanged). smem = 48KB static.
// ---------------------------------------------------------------------------
__global__ void __launch_bounds__(256) k2_dwom(const float* __restrict__ x,
                                               const float* __restrict__ dw_w,
                                               const float* __restrict__ dw_b,
                                               const float* __restrict__ om_w,
                                               const float* __restrict__ om_b) {
    __shared__ float dws[4096];       // [px][c] swizzled
    __shared__ unsigned Bh[4096], Bl[4096];  // om weights [n][k] swizzled
    int t = threadIdx.x;
    for (int i = t; i < 4096; i += 256) {
        int n = i >> 6, k = i & 63;
        float wv = (n < 54) ? om_w[n * 64 + k] : 0.f;
        unsigned h, l; split_tf(wv, h, l);
        int idx = n * 64 + (k ^ SW(n));
        Bh[idx] = h; Bl[idx] = l;
    }

    int bb = blockIdx.x >> 8;
    int p0 = (blockIdx.x & 255) * 64;
    int h = p0 >> 7;
    int w0 = p0 & 127;
    const float* xb = x + (size_t)bb * (PB * 64);

    {
        int c = t & 63;
        int pg = t >> 6;
        float wk[9];
#pragma unroll
        for (int k = 0; k < 9; k++) wk[k] = dw_w[c * 9 + k];
        float bias = dw_b[c];
        int wstart = w0 + pg * 16;
        const float* xc = xb + c;
        float v[3][3];
#pragma unroll
        for (int ky = 0; ky < 3; ky++) {
            int yy = h + ky - 1;
            bool yok = (unsigned)yy < 128u;
            int xm1 = wstart - 1;
            v[ky][1] = (yok && (unsigned)xm1 < 128u)
                           ? __ldg(xc + ((size_t)((yy << 7) + xm1) << 6)) : 0.f;
            v[ky][2] = yok ? __ldg(xc + ((size_t)((yy << 7) + wstart) << 6)) : 0.f;
        }
        for (int i = 0; i < 16; i++) {
            int w = wstart + i;
            int xp1 = w + 1;
#pragma unroll
            for (int ky = 0; ky < 3; ky++) {
                int yy = h + ky - 1;
                v[ky][0] = v[ky][1];
                v[ky][1] = v[ky][2];
                v[ky][2] = ((unsigned)yy < 128u && (unsigned)xp1 < 128u)
                               ? __ldg(xc + ((size_t)((yy << 7) + xp1) << 6)) : 0.f;
            }
            float acc = bias;
#pragma unroll
            for (int ky = 0; ky < 3; ky++)
#pragma unroll
                for (int kx = 0; kx < 3; kx++)
                    acc = fmaf(v[ky][kx], wk[ky * 3 + kx], acc);
            int px = pg * 16 + i;
            dws[px * 64 + (c ^ SW(px))] = acc;
        }
    }
    __syncthreads();

    int w = t >> 5;
    if (w < 7) {
        int lane = t & 31;
        int r = lane >> 2, q = lane & 3;
        float acc[4][4];
#pragma unroll
        for (int mt = 0; mt < 4; mt++)
#pragma unroll
            for (int i = 0; i < 4; i++) acc[mt][i] = 0.f;
        int n0 = w * 8 + r;
        int nbase = n0 * 64, ns = SW(n0);
#pragma unroll
        for (int kc = 0; kc < 8; kc++) {
            int k = kc * 8 + q;
            unsigned bh0 = Bh[nbase + (k ^ ns)];
            unsigned bh1 = Bh[nbase + ((k + 4) ^ ns)];
            unsigned bl0 = Bl[nbase + (k ^ ns)];
            unsigned bl1 = Bl[nbase + ((k + 4) ^ ns)];
#pragma unroll
            for (int mt = 0; mt < 4; mt++) {
                int rA = mt * 16 + r, rB = rA + 8;
                float a0f = dws[rA * 64 + (k ^ SW(rA))];
                float a1f = dws[rB * 64 + (k ^ SW(rB))];
                float a2f = dws[rA * 64 + ((k + 4) ^ SW(rA))];
                float a3f = dws[rB * 64 + ((k + 4) ^ SW(rB))];
                unsigned ah0, ah1, ah2, ah3, al0, al1, al2, al3;
                split_tf(a0f, ah0, al0); split_tf(a1f, ah1, al1);
                split_tf(a2f, ah2, al2); split_tf(a3f, ah3, al3);
                mma8(acc[mt], ah0, ah1, ah2, ah3, bh0, bh1);
                mma8(acc[mt], ah0, ah1, ah2, ah3, bl0, bl1);
                mma8(acc[mt], al0, al1, al2, al3, bh0, bh1);
            }
        }
        int jc = w * 8 + 2 * q;
        if (jc < 54) {
            float2 ob2 = __ldg((const float2*)(om_b + jc));
#pragma unroll
            for (int mt = 0; mt < 4; mt++) {
                int pxA = p0 + mt * 16 + r;
                size_t baseA = ((size_t)bb * PB + pxA) * 54;
                *(float2*)&g_om[baseA + jc] =
                    make_float2(acc[mt][0] + ob2.x, acc[mt][1] + ob2.y);
                *(float2*)&g_om[baseA + 54 * 8 + jc] =
                    make_float2(acc[mt][2] + ob2.x, acc[mt][3] + ob2.y);
            }
        }
    }
}

// ---------------------------------------------------------------------------
// K3: DCN. Gather is warp-parallel + branch-free: lane k of each 8-lane
// subgroup computes tap-k geometry (lane 0 also tap 8) with OOB clamp/swap
// (invalid corner -> weight 0, indices always in-bounds), broadcast via shfl.
// Then op GEMM (3xTF32 mma) + in-register pair fold + BN + ReLU.
// ---------------------------------------------------------------------------
__device__ __forceinline__ void geom(const float* __restrict__ omp, int h, int w,
                                     int k, int& lin, float4& w4) {
    float ox = omp[2 * k], oy = omp[2 * k + 1], m = omp[18 + k];
    float ix = (float)w + ((float)(k - (k / 3) * 3) - 1.0f + ox) * 2.0f;
    float iy = (float)h + ((float)(k / 3) - 1.0f + oy) * 2.0f;
    float xf = floorf(ix), yf = floorf(iy);
    float tx = ix - xf, ty = iy - yf;
    int x0 = (int)xf, y0 = (int)yf;
    float wx0 = ((unsigned)x0 < 128u) ? (1.f - tx) : 0.f;
    float wx1 = ((unsigned)(x0 + 1) < 128u) ? tx : 0.f;
    int x0c = x0;
    if (x0 < 0)        { wx0 = wx1; wx1 = 0.f; x0c = 0; }
    else if (x0 > 126) { wx1 = wx0; wx0 = 0.f; x0c = 126; }
    float wy0 = ((unsigned)y0 < 128u) ? (1.f - ty) : 0.f;
    float wy1 = ((unsigned)(y0 + 1) < 128u) ? ty : 0.f;
    int y0c = y0;
    if (y0 < 0)        { wy0 = wy1; wy1 = 0.f; y0c = 0; }
    else if (y0 > 126) { wy1 = wy0; wy0 = 0.f; y0c = 126; }
    lin = (y0c << 7) + x0c;
    w4 = make_float4(wy0 * wx0 * m, wy0 * wx1 * m, wy1 * wx0 * m, wy1 * wx1 * m);
}

__global__ void __launch_bounds__(256) k3_dcn(const float* __restrict__ op_w,
                                              const float* __restrict__ op_b,
                                              const float* __restrict__ bn_g,
                                              const float* __restrict__ bn_b,
                                              const float* __restrict__ bn_m,
                                              const float* __restrict__ bn_v,
                                              float* __restrict__ out) {
    __shared__ unsigned Bh[4096], Bl[4096];  // op weights [n][k] swizzled
    __shared__ float cs[2048];               // core [pl][c] swizzled (32x64)
    __shared__ float oms[32 * 54];
    int t = threadIdx.x;
    for (int i = t; i < 4096; i += 256) {
        int n = i >> 6, k = i & 63;
        unsigned h, l; split_tf(op_w[i], h, l);
        int idx = n * 64 + (k ^ SW(n));
        Bh[idx] = h; Bl[idx] = l;
    }

    int bb = blockIdx.x >> 9;
    int p0 = (blockIdx.x & 511) * 16;       // in [0, 8192)

    for (int i = t; i < 32 * 54; i += 256) {
        int pl = i / 54;
        int j = i - pl * 54;
        int p = p0 + ((pl < 16) ? pl : (pl - 16 + 8192));
        oms[pl * 54 + j] = g_om[((size_t)bb * PB + p) * 54 + j];
    }
    __syncthreads();

    // Gather: 16 lanes per pixel (2 groups x 8 lanes x 4 ch), 2 passes.
    {
        int lane = t & 31;
        int sub = t & 15;
        int g = sub >> 3;
        int d0 = (sub & 7) * 4;
        int plh = t >> 4;
        int cb = g * 32 + d0;
        int ksub = lane & 7;       // geometry duty tap
        int gbase = lane & 24;     // subgroup base lane
        const float* vb = g_value + (size_t)bb * (PB * 64) + cb;
        const unsigned FULL = 0xFFFFFFFFu;
#pragma unroll
        for (int pass = 0; pass < 2; pass++) {
            int pl = plh + pass * 16;
            int p = p0 + plh + pass * 8192;
            int h = p >> 7;
            int w = p & 127;
            const float* omp = &oms[pl * 54 + g * 27];
            int lin1, lin2 = 0;
            float4 w41, w42 = make_float4(0.f, 0.f, 0.f, 0.f);
            geom(omp, h, w, ksub, lin1, w41);
            if (ksub == 0) geom(omp, h, w, 8, lin2, w42);

            float a0 = 0.f, a1 = 0.f, a2 = 0.f, a3 = 0.f;
#pragma unroll
            for (int k = 0; k < 9; k++) {
                int src = gbase + ((k < 8) ? k : 0);
                int lin  = __shfl_sync(FULL, (k < 8) ? lin1 : lin2, src);
                float c0 = __shfl_sync(FULL, (k < 8) ? w41.x : w42.x, src);
                float c1 = __shfl_sync(FULL, (k < 8) ? w41.y : w42.y, src);
                float c2 = __shfl_sync(FULL, (k < 8) ? w41.z : w42.z, src);
                float c3 = __shfl_sync(FULL, (k < 8) ? w41.w : w42.w, src);
                const float* qp = vb + (size_t)lin * 64;
                float4 v00 = __ldg((const float4*)(qp));
                float4 v01 = __ldg((const float4*)(qp + 64));
                float4 v10 = __ldg((const float4*)(qp + 8192));
                float4 v11 = __ldg((const float4*)(qp + 8256));
                a0 = fmaf(c0, v00.x, a0); a1 = fmaf(c0, v00.y, a1);
                a2 = fmaf(c0, v00.z, a2); a3 = fmaf(c0, v00.w, a3);
                a0 = fmaf(c1, v01.x, a0); a1 = fmaf(c1, v01.y, a1);
                a2 = fmaf(c1, v01.z, a2); a3 = fmaf(c1, v01.w, a3);
                a0 = fmaf(c2, v10.x, a0); a1 = fmaf(c2, v10.y, a1);
                a2 = fmaf(c2, v10.z, a2); a3 = fmaf(c2, v10.w, a3);
                a0 = fmaf(c3, v11.x, a0); a1 = fmaf(c3, v11.y, a1);
                a2 = fmaf(c3, v11.z, a2); a3 = fmaf(c3, v11.w, a3);
            }
            *(float4*)&cs[pl * 64 + (cb ^ SW(pl))] = make_float4(a0, a1, a2, a3);
        }
    }
    __syncthreads();

    // op GEMM via mma: warp w -> n-tile w; m-tiles rows 0-15 (A) and 16-31 (B).
    {
        int w = t >> 5, lane = t & 31;
        int r = lane >> 2, q = lane & 3;
        float accA[4] = {0.f, 0.f, 0.f, 0.f};
        float accB[4] = {0.f, 0.f, 0.f, 0.f};
        int n0 = w * 8 + r;
        int nbase = n0 * 64, ns = SW(n0);
#pragma unroll
        for (int kc = 0; kc < 8; kc++) {
            int k = kc * 8 + q;
            unsigned bh0 = Bh[nbase + (k ^ ns)];
            unsigned bh1 = Bh[nbase + ((k + 4) ^ ns)];
            unsigned bl0 = Bl[nbase + (k ^ ns)];
            unsigned bl1 = Bl[nbase + ((k + 4) ^ ns)];
            {
                int rA = r, rB = r + 8;
                float a0f = cs[rA * 64 + (k ^ SW(rA))];
                float a1f = cs[rB * 64 + (k ^ SW(rB))];
                float a2f = cs[rA * 64 + ((k + 4) ^ SW(rA))];
                float a3f = cs[rB * 64 + ((k + 4) ^ SW(rB))];
                unsigned ah0, ah1, ah2, ah3, al0, al1, al2, al3;
                split_tf(a0f, ah0, al0); split_tf(a1f, ah1, al1);
                split_tf(a2f, ah2, al2); split_tf(a3f, ah3, al3);
                mma8(accA, ah0, ah1, ah2, ah3, bh0, bh1);
                mma8(accA, ah0, ah1, ah2, ah3, bl0, bl1);
                mma8(accA, al0, al1, al2, al3, bh0, bh1);
            }
            {
                int rA = 16 + r, rB = 24 + r;
                float a0f = cs[rA * 64 + (k ^ SW(rA))];
                float a1f = cs[rB * 64 + (k ^ SW(rB))];
                float a2f = cs[rA * 64 + ((k + 4) ^ SW(rA))];
                float a3f = cs[rB * 64 + ((k + 4) ^ SW(rB))];
                unsigned ah0, ah1, ah2, ah3, al0, al1, al2, al3;
                split_tf(a0f, ah0, al0); split_tf(a1f, ah1, al1);
                split_tf(a2f, ah2, al2); split_tf(a3f, ah3, al3);
                mma8(accB, ah0, ah1, ah2, ah3, bh0, bh1);
                mma8(accB, ah0, ah1, ah2, ah3, bl0, bl1);
                mma8(accB, al0, al1, al2, al3, bh0, bh1);
            }
        }
        int jc = w * 8 + 2 * q;
        float2 ob2 = __ldg((const float2*)(op_b + jc));
        int cz = p0 >> 8;
        float sA = __ldg(bn_g + cz) * rsqrtf(__ldg(bn_v + cz) + 1e-5f);
        float sB = fmaf(-sA, __ldg(bn_m + cz), __ldg(bn_b + cz));
#pragma unroll
        for (int half = 0; half < 2; half++) {
            int rr = r + half * 8;
            int i0 = half * 2, i1 = half * 2 + 1;
            int p = p0 + rr;
            float z0 = fmaf(0.5f * (accA[i0] + accB[i0]) + ob2.x, sA, sB);
            float z1 = fmaf(0.5f * (accA[i1] + accB[i1]) + ob2.y, sA, sB);
            int hh = (p >> 1) & 127;
            int qq = p & 1;
            size_t base = (((size_t)bb * 32 + cz) * 128 + hh) * 128 + (qq << 6);
            *(float2*)&out[base + jc] =
                make_float2(fmaxf(z0, 0.f), fmaxf(z1, 0.f));
        }
    }
}

// ---------------------------------------------------------------------------
extern "C" void kernel_launch(void* const* d_in, const int* in_sizes, int n_in,
                              void* d_out, int out_size) {
    const float* x    = (const float*)d_in[0];
    const float* vp_w = (const float*)d_in[1];
    const float* vp_b = (const float*)d_in[2];
    const float* dw_w = (const float*)d_in[3];
    const float* dw_b = (const float*)d_in[4];
    const float* om_w = (const float*)d_in[5];
    const float* om_b = (const float*)d_in[6];
    const float* op_w = (const float*)d_in[7];
    const float* op_b = (const float*)d_in[8];
    const float* bn_g = (const float*)d_in[9];
    const float* bn_b = (const float*)d_in[10];
    const float* bn_m = (const float*)d_in[11];
    const float* bn_v = (const float*)d_in[12];
    float* out = (float*)d_out;

    k1_valproj<<<NROWS / 64, 256>>>(x, vp_w, vp_b);
    k2_dwom<<<NB * (PB / 64), 256>>>(x, dw_w, dw_b, om_w, om_b);
    k3_dcn<<<NB * 512, 256>>>(op_w, op_b, bn_g, bn_b, bn_m, bn_v, out);
}

// round 9
// speedup vs baseline: 1.1612x; 1.1612x over previous
#include <cuda_runtime.h>
#include <cuda_bf16.h>

// Problem constants: B=8, C=64, H=W=128, G=2, D=32, K=9, OS=2.0
#define PB 16384
#define NB 8
#define NROWS (NB * PB)

__device__ float g_value[NB * PB * 64];   // (b,p,64)
__device__ float g_om[NB * PB * 54];      // (b,p,54)

// XOR swizzle: rows stride 64 floats, swizzle k by row to decollide banks.
#define SW(r) (((r) & 7) << 2)

__device__ __forceinline__ unsigned f2tf(float f) {
    unsigned r; asm("cvt.rna.tf32.f32 %0, %1;" : "=r"(r) : "f"(f)); return r;
}
__device__ __forceinline__ void split_tf(float f, unsigned& hi, unsigned& lo) {
    hi = f2tf(f);
    lo = f2tf(f - __uint_as_float(hi));
}
__device__ __forceinline__ void mma8(float* c, unsigned a0, unsigned a1,
                                     unsigned a2, unsigned a3,
                                     unsigned b0, unsigned b1) {
    asm("mma.sync.aligned.m16n8k8.row.col.f32.tf32.tf32.f32 "
        "{%0,%1,%2,%3},{%4,%5,%6,%7},{%8,%9},{%0,%1,%2,%3};"
        : "+f"(c[0]), "+f"(c[1]), "+f"(c[2]), "+f"(c[3])
        : "r"(a0), "r"(a1), "r"(a2), "r"(a3), "r"(b0), "r"(b1));
}

// ---------------------------------------------------------------------------
// K1: value projection via 3xTF32 mma (round-4 version; 38.2us known-best).
// ---------------------------------------------------------------------------
__global__ void __launch_bounds__(256) k1_valproj(const float* __restrict__ x,
                                                  const float* __restrict__ vp_w,
                                                  const float* __restrict__ vp_b) {
    __shared__ unsigned Bh[4096], Bl[4096];   // [n][k] swizzled
    int t = threadIdx.x;
    for (int i = t; i < 4096; i += 256) {
        int n = i >> 6, k = i & 63;
        unsigned h, l; split_tf(vp_w[i], h, l);
        int idx = n * 64 + (k ^ SW(n));
        Bh[idx] = h; Bl[idx] = l;
    }
    __syncthreads();

    int w = t >> 5, lane = t & 31;
    int r = lane >> 2, q = lane & 3;
    size_t row0 = (size_t)blockIdx.x * 128 + w * 16;
    const float* ar = x + (row0 + r) * 64;

    float acc[8][4];
#pragma unroll
    for (int nt = 0; nt < 8; nt++)
#pragma unroll
        for (int i = 0; i < 4; i++) acc[nt][i] = 0.f;

#pragma unroll
    for (int kc = 0; kc < 8; kc++) {
        int k = kc * 8 + q;
        float a0f = __ldg(ar + k);
        float a1f = __ldg(ar + 512 + k);
        float a2f = __ldg(ar + k + 4);
        float a3f = __ldg(ar + 512 + k + 4);
        unsigned ah0, ah1, ah2, ah3, al0, al1, al2, al3;
        split_tf(a0f, ah0, al0); split_tf(a1f, ah1, al1);
        split_tf(a2f, ah2, al2); split_tf(a3f, ah3, al3);
#pragma unroll
        for (int nt = 0; nt < 8; nt++) {
            int n0 = nt * 8 + r;
            int base = n0 * 64, s = SW(n0);
            unsigned bh0 = Bh[base + (k ^ s)];
            unsigned bh1 = Bh[base + ((k + 4) ^ s)];
            unsigned bl0 = Bl[base + (k ^ s)];
            unsigned bl1 = Bl[base + ((k + 4) ^ s)];
            mma8(acc[nt], ah0, ah1, ah2, ah3, bh0, bh1);
            mma8(acc[nt], ah0, ah1, ah2, ah3, bl0, bl1);
            mma8(acc[nt], al0, al1, al2, al3, bh0, bh1);
        }
    }
#pragma unroll
    for (int nt = 0; nt < 8; nt++) {
        int jc = nt * 8 + 2 * q;
        float2 b2 = __ldg((const float2*)(vp_b + jc));
        *(float2*)&g_value[(row0 + r) * 64 + jc] =
            make_float2(acc[nt][0] + b2.x, acc[nt][1] + b2.y);
        *(float2*)&g_value[(row0 + r + 8) * 64 + jc] =
            make_float2(acc[nt][2] + b2.x, acc[nt][3] + b2.y);
    }
}

// ---------------------------------------------------------------------------
// K2: depthwise 3x3 conv (sliding window) + om GEMM via 3xTF32 mma.
// (round-4 version, unchanged). smem = 48KB static.
// ---------------------------------------------------------------------------
__global__ void __launch_bounds__(256) k2_dwom(const float* __restrict__ x,
                                               const float* __restrict__ dw_w,
                                               const float* __restrict__ dw_b,
                                               const float* __restrict__ om_w,
                                               const float* __restrict__ om_b) {
    __shared__ float dws[4096];       // [px][c] swizzled
    __shared__ unsigned Bh[4096], Bl[4096];  // om weights [n][k] swizzled
    int t = threadIdx.x;
    for (int i = t; i < 4096; i += 256) {
        int n = i >> 6, k = i & 63;
        float wv = (n < 54) ? om_w[n * 64 + k] : 0.f;
        unsigned h, l; split_tf(wv, h, l);
        int idx = n * 64 + (k ^ SW(n));
        Bh[idx] = h; Bl[idx] = l;
    }

    int bb = blockIdx.x >> 8;
    int p0 = (blockIdx.x & 255) * 64;
    int h = p0 >> 7;
    int w0 = p0 & 127;
    const float* xb = x + (size_t)bb * (PB * 64);

    {
        int c = t & 63;
        int pg = t >> 6;
        float wk[9];
#pragma unroll
        for (int k = 0; k < 9; k++) wk[k] = dw_w[c * 9 + k];
        float bias = dw_b[c];
        int wstart = w0 + pg * 16;
        const float* xc = xb + c;
        float v[3][3];
#pragma unroll
        for (int ky = 0; ky < 3; ky++) {
            int yy = h + ky - 1;
            bool yok = (unsigned)yy < 128u;
            int xm1 = wstart - 1;
            v[ky][1] = (yok && (unsigned)xm1 < 128u)
                           ? __ldg(xc + ((size_t)((yy << 7) + xm1) << 6)) : 0.f;
            v[ky][2] = yok ? __ldg(xc + ((size_t)((yy << 7) + wstart) << 6)) : 0.f;
        }
        for (int i = 0; i < 16; i++) {
            int w = wstart + i;
            int xp1 = w + 1;
#pragma unroll
            for (int ky = 0; ky < 3; ky++) {
                int yy = h + ky - 1;
                v[ky][0] = v[ky][1];
                v[ky][1] = v[ky][2];
                v[ky][2] = ((unsigned)yy < 128u && (unsigned)xp1 < 128u)
                               ? __ldg(xc + ((size_t)((yy << 7) + xp1) << 6)) : 0.f;
            }
            float acc = bias;
#pragma unroll
            for (int ky = 0; ky < 3; ky++)
#pragma unroll
                for (int kx = 0; kx < 3; kx++)
                    acc = fmaf(v[ky][kx], wk[ky * 3 + kx], acc);
            int px = pg * 16 + i;
            dws[px * 64 + (c ^ SW(px))] = acc;
        }
    }
    __syncthreads();

    int w = t >> 5;
    if (w < 7) {
        int lane = t & 31;
        int r = lane >> 2, q = lane & 3;
        float acc[4][4];
#pragma unroll
        for (int mt = 0; mt < 4; mt++)
#pragma unroll
            for (int i = 0; i < 4; i++) acc[mt][i] = 0.f;
        int n0 = w * 8 + r;
        int nbase = n0 * 64, ns = SW(n0);
#pragma unroll
        for (int kc = 0; kc < 8; kc++) {
            int k = kc * 8 + q;
            unsigned bh0 = Bh[nbase + (k ^ ns)];
            unsigned bh1 = Bh[nbase + ((k + 4) ^ ns)];
            unsigned bl0 = Bl[nbase + (k ^ ns)];
            unsigned bl1 = Bl[nbase + ((k + 4) ^ ns)];
#pragma unroll
            for (int mt = 0; mt < 4; mt++) {
                int rA = mt * 16 + r, rB = rA + 8;
                float a0f = dws[rA * 64 + (k ^ SW(rA))];
                float a1f = dws[rB * 64 + (k ^ SW(rB))];
                float a2f = dws[rA * 64 + ((k + 4) ^ SW(rA))];
                float a3f = dws[rB * 64 + ((k + 4) ^ SW(rB))];
                unsigned ah0, ah1, ah2, ah3, al0, al1, al2, al3;
                split_tf(a0f, ah0, al0); split_tf(a1f, ah1, al1);
                split_tf(a2f, ah2, al2); split_tf(a3f, ah3, al3);
                mma8(acc[mt], ah0, ah1, ah2, ah3, bh0, bh1);
                mma8(acc[mt], ah0, ah1, ah2, ah3, bl0, bl1);
                mma8(acc[mt], al0, al1, al2, al3, bh0, bh1);
            }
        }
        int jc = w * 8 + 2 * q;
        if (jc < 54) {
            float2 ob2 = __ldg((const float2*)(om_b + jc));
#pragma unroll
            for (int mt = 0; mt < 4; mt++) {
                int pxA = p0 + mt * 16 + r;
                size_t baseA = ((size_t)bb * PB + pxA) * 54;
                *(float2*)&g_om[baseA + jc] =
                    make_float2(acc[mt][0] + ob2.x, acc[mt][1] + ob2.y);
                *(float2*)&g_om[baseA + 54 * 8 + jc] =
                    make_float2(acc[mt][2] + ob2.x, acc[mt][3] + ob2.y);
            }
        }
    }
}

// ---------------------------------------------------------------------------
// K3: DCN with phase-overlapped STATIC smem (40KB, no dynamic alloc).
//   pool[0..8192):   phase W+gather -> s_w4 (2304 w) + s_lin (576 w)
//                    after gather   -> Bh (4096 w) + Bl (4096 w)   (reused)
//   pool[8192..10240): cs (32x64 core tile, swizzled)
// Phase W precomputes clamped base + 4 pre-masked bilinear weights (OOB
// corner -> weight 0, indices always valid); gather is branch-free
// LDS + 4x LDG.128 + 16 FFMA per tap. Then op GEMM (3xTF32 mma) +
// in-register pair fold + BN + ReLU.
// ---------------------------------------------------------------------------
__global__ void __launch_bounds__(256) k3_dcn(const float* __restrict__ op_w,
                                              const float* __restrict__ op_b,
                                              const float* __restrict__ bn_g,
                                              const float* __restrict__ bn_b,
                                              const float* __restrict__ bn_m,
                                              const float* __restrict__ bn_v,
                                              float* __restrict__ out) {
    __shared__ __align__(16) unsigned pool[10240];   // 40KB
    float4* s_w4 = (float4*)pool;            // 576 float4 = 2304 words
    int* s_lin = (int*)(pool + 2304);        // 576 words (ends at 2880)
    unsigned* Bh = pool;                     // [0..4096)   after gather
    unsigned* Bl = pool + 4096;              // [4096..8192) after gather
    float* cs = (float*)(pool + 8192);       // 2048 words (32x64 swizzled)
    int t = threadIdx.x;

    int bb = blockIdx.x >> 9;
    int p0 = (blockIdx.x & 511) * 16;        // in [0, 8192)

    // Phase W: 32 px x 2 g x 9 k = 576 geometry items.
    for (int it = t; it < 576; it += 256) {
        int pl = it / 18;
        int rem = it - pl * 18;
        int g = rem / 9;
        int k = rem - g * 9;
        int p = p0 + ((pl < 16) ? pl : (pl - 16 + 8192));
        int h = p >> 7, w = p & 127;
        const float* om = g_om + ((size_t)bb * PB + p) * 54 + g * 27;
        float ox = om[2 * k], oy = om[2 * k + 1], m = om[18 + k];
        float ix = (float)w + ((float)(k - (k / 3) * 3) - 1.0f + ox) * 2.0f;
        float iy = (float)h + ((float)(k / 3) - 1.0f + oy) * 2.0f;
        float xf = floorf(ix), yf = floorf(iy);
        float tx = ix - xf, ty = iy - yf;
        int x0 = (int)xf, y0 = (int)yf;
        float wx0 = ((unsigned)x0 < 128u) ? (1.f - tx) : 0.f;
        float wx1 = ((unsigned)(x0 + 1) < 128u) ? tx : 0.f;
        int x0c = x0;
        if (x0 < 0)        { wx0 = wx1; wx1 = 0.f; x0c = 0; }
        else if (x0 > 126) { wx1 = wx0; wx0 = 0.f; x0c = 126; }
        float wy0 = ((unsigned)y0 < 128u) ? (1.f - ty) : 0.f;
        float wy1 = ((unsigned)(y0 + 1) < 128u) ? ty : 0.f;
        int y0c = y0;
        if (y0 < 0)        { wy0 = wy1; wy1 = 0.f; y0c = 0; }
        else if (y0 > 126) { wy1 = wy0; wy0 = 0.f; y0c = 126; }
        s_lin[it] = (y0c << 7) + x0c;
        s_w4[it] = make_float4(wy0 * wx0 * m, wy0 * wx1 * m,
                               wy1 * wx0 * m, wy1 * wx1 * m);
    }
    __syncthreads();

    // Gather: 16 lanes per pixel (4 channels each), 2 passes over 32 px.
    {
        int sub = t & 15;
        int g = sub >> 3;
        int d0 = (sub & 7) * 4;
        int plh = t >> 4;
        int cb = g * 32 + d0;
        const float* vb = g_value + (size_t)bb * (PB * 64) + cb;
#pragma unroll
        for (int pass = 0; pass < 2; pass++) {
            int pl = plh + pass * 16;
            int ib = pl * 18 + g * 9;
            float a0 = 0.f, a1 = 0.f, a2 = 0.f, a3 = 0.f;
#pragma unroll
            for (int k = 0; k < 9; k++) {
                int lin = s_lin[ib + k];
                float4 w4 = s_w4[ib + k];
                const float* q = vb + (size_t)lin * 64;
                float4 v00 = __ldg((const float4*)(q));
                float4 v01 = __ldg((const float4*)(q + 64));
                float4 v10 = __ldg((const float4*)(q + 8192));
                float4 v11 = __ldg((const float4*)(q + 8256));
                a0 = fmaf(w4.x, v00.x, a0); a1 = fmaf(w4.x, v00.y, a1);
                a2 = fmaf(w4.x, v00.z, a2); a3 = fmaf(w4.x, v00.w, a3);
                a0 = fmaf(w4.y, v01.x, a0); a1 = fmaf(w4.y, v01.y, a1);
                a2 = fmaf(w4.y, v01.z, a2); a3 = fmaf(w4.y, v01.w, a3);
                a0 = fmaf(w4.z, v10.x, a0); a1 = fmaf(w4.z, v10.y, a1);
                a2 = fmaf(w4.z, v10.z, a2); a3 = fmaf(w4.z, v10.w, a3);
                a0 = fmaf(w4.w, v11.x, a0); a1 = fmaf(w4.w, v11.y, a1);
                a2 = fmaf(w4.w, v11.z, a2); a3 = fmaf(w4.w, v11.w, a3);
            }
            *(float4*)&cs[pl * 64 + (cb ^ SW(pl))] = make_float4(a0, a1, a2, a3);
        }
    }
    __syncthreads();

    // Load op weights (hi/lo tf32) into the now-dead geometry region.
    for (int i = t; i < 4096; i += 256) {
        int n = i >> 6, k = i & 63;
        unsigned h, l; split_tf(op_w[i], h, l);
        int idx = n * 64 + (k ^ SW(n));
        Bh[idx] = h; Bl[idx] = l;
    }
    __syncthreads();

    // op GEMM via mma: warp w -> n-tile w; m-tiles rows 0-15 (A) and 16-31 (B).
    {
        int w = t >> 5, lane = t & 31;
        int r = lane >> 2, q = lane & 3;
        float accA[4] = {0.f, 0.f, 0.f, 0.f};
        float accB[4] = {0.f, 0.f, 0.f, 0.f};
        int n0 = w * 8 + r;
        int nbase = n0 * 64, ns = SW(n0);
#pragma unroll
        for (int kc = 0; kc < 8; kc++) {
            int k = kc * 8 + q;
            unsigned bh0 = Bh[nbase + (k ^ ns)];
            unsigned bh1 = Bh[nbase + ((k + 4) ^ ns)];
            unsigned bl0 = Bl[nbase + (k ^ ns)];
            unsigned bl1 = Bl[nbase + ((k + 4) ^ ns)];
            {
                int rA = r, rB = r + 8;
                float a0f = cs[rA * 64 + (k ^ SW(rA))];
                float a1f = cs[rB * 64 + (k ^ SW(rB))];
                float a2f = cs[rA * 64 + ((k + 4) ^ SW(rA))];
                float a3f = cs[rB * 64 + ((k + 4) ^ SW(rB))];
                unsigned ah0, ah1, ah2, ah3, al0, al1, al2, al3;
                split_tf(a0f, ah0, al0); split_tf(a1f, ah1, al1);
                split_tf(a2f, ah2, al2); split_tf(a3f, ah3, al3);
                mma8(accA, ah0, ah1, ah2, ah3, bh0, bh1);
                mma8(accA, ah0, ah1, ah2, ah3, bl0, bl1);
                mma8(accA, al0, al1, al2, al3, bh0, bh1);
            }
            {
                int rA = 16 + r, rB = 24 + r;
                float a0f = cs[rA * 64 + (k ^ SW(rA))];
                float a1f = cs[rB * 64 + (k ^ SW(rB))];
                float a2f = cs[rA * 64 + ((k + 4) ^ SW(rA))];
                float a3f = cs[rB * 64 + ((k + 4) ^ SW(rB))];
                unsigned ah0, ah1, ah2, ah3, al0, al1, al2, al3;
                split_tf(a0f, ah0, al0); split_tf(a1f, ah1, al1);
                split_tf(a2f, ah2, al2); split_tf(a3f, ah3, al3);
                mma8(accB, ah0, ah1, ah2, ah3, bh0, bh1);
                mma8(accB, ah0, ah1, ah2, ah3, bl0, bl1);
                mma8(accB, al0, al1, al2, al3, bh0, bh1);
            }
        }
        int jc = w * 8 + 2 * q;
        float2 ob2 = __ldg((const float2*)(op_b + jc));
        int cz = p0 >> 8;
        float sA = __ldg(bn_g + cz) * rsqrtf(__ldg(bn_v + cz) + 1e-5f);
        float sB = fmaf(-sA, __ldg(bn_m + cz), __ldg(bn_b + cz));
#pragma unroll
        for (int half = 0; half < 2; half++) {
            int rr = r + half * 8;
            int i0 = half * 2, i1 = half * 2 + 1;
            int p = p0 + rr;
            float z0 = fmaf(0.5f * (accA[i0] + accB[i0]) + ob2.x, sA, sB);
            float z1 = fmaf(0.5f * (accA[i1] + accB[i1]) + ob2.y, sA, sB);
            int hh = (p >> 1) & 127;
            int qq = p & 1;
            size_t base = (((size_t)bb * 32 + cz) * 128 + hh) * 128 + (qq << 6);
            *(float2*)&out[base + jc] =
                make_float2(fmaxf(z0, 0.f), fmaxf(z1, 0.f));
        }
    }
}

// ---------------------------------------------------------------------------
extern "C" void kernel_launch(void* const* d_in, const int* in_sizes, int n_in,
                              void* d_out, int out_size) {
    const float* x    = (const float*)d_in[0];
    const float* vp_w = (const float*)d_in[1];
    const float* vp_b = (const float*)d_in[2];
    const float* dw_w = (const float*)d_in[3];
    const float* dw_b = (const float*)d_in[4];
    const float* om_w = (const float*)d_in[5];
    const float* om_b = (const float*)d_in[6];
    const float* op_w = (const float*)d_in[7];
    const float* op_b = (const float*)d_in[8];
    const float* bn_g = (const float*)d_in[9];
    const float* bn_b = (const float*)d_in[10];
    const float* bn_m = (const float*)d_in[11];
    const float* bn_v = (const float*)d_in[12];
    float* out = (float*)d_out;

    // k2 launched FIRST (independent of k1) so ncu's fixed capture index
    // lands on a kernel we haven't profiled yet.
    k2_dwom<<<NB * (PB / 64), 256>>>(x, dw_w, dw_b, om_w, om_b);
    k1_valproj<<<NROWS / 128, 256>>>(x, vp_w, vp_b);
    k3_dcn<<<NB * 512, 256>>>(op_w, op_b, bn_g, bn_b, bn_m, bn_v, out);
}

// round 10
// speedup vs baseline: 1.2451x; 1.0722x over previous
#include <cuda_runtime.h>
#include <cuda_bf16.h>

// Problem constants: B=8, C=64, H=W=128, G=2, D=32, K=9, OS=2.0
#define PB 16384
#define NB 8
#define NROWS (NB * PB)

__device__ float g_value[NB * PB * 64];   // (b,p,64)
__device__ float g_om[NB * PB * 54];      // (b,p,54)
__device__ uint2 g_omw2[4096];            // om weights [n][k] pre-split (hi,lo), n>=54 zero
__device__ uint2 g_opw2[4096];            // op weights [n][k] pre-split (hi,lo)

// XOR swizzle: rows stride 64 elements, swizzle k by row to decollide banks.
#define SW(r) (((r) & 7) << 2)

__device__ __forceinline__ unsigned f2tf(float f) {
    unsigned r; asm("cvt.rna.tf32.f32 %0, %1;" : "=r"(r) : "f"(f)); return r;
}
__device__ __forceinline__ void split_tf(float f, unsigned& hi, unsigned& lo) {
    hi = f2tf(f);
    lo = f2tf(f - __uint_as_float(hi));
}
__device__ __forceinline__ void mma8(float* c, unsigned a0, unsigned a1,
                                     unsigned a2, unsigned a3,
                                     unsigned b0, unsigned b1) {
    asm("mma.sync.aligned.m16n8k8.row.col.f32.tf32.tf32.f32 "
        "{%0,%1,%2,%3},{%4,%5,%6,%7},{%8,%9},{%0,%1,%2,%3};"
        : "+f"(c[0]), "+f"(c[1]), "+f"(c[2]), "+f"(c[3])
        : "r"(a0), "r"(a1), "r"(a2), "r"(a3), "r"(b0), "r"(b1));
}

// ---------------------------------------------------------------------------
// K0: pre-split om_w (padded to 64 rows) and op_w into global hi/lo tables.
// 32 blocks x 256 threads = 8192 elements.
// ---------------------------------------------------------------------------
__global__ void __launch_bounds__(256) k0_split(const float* __restrict__ om_w,
                                                const float* __restrict__ op_w) {
    int i = blockIdx.x * 256 + threadIdx.x;
    if (i < 4096) {
        int n = i >> 6, k = i & 63;
        float wv = (n < 54) ? om_w[n * 64 + k] : 0.f;
        unsigned h, l; split_tf(wv, h, l);
        g_omw2[i] = make_uint2(h, l);
    } else {
        int j = i - 4096;
        unsigned h, l; split_tf(op_w[j], h, l);
        g_opw2[j] = make_uint2(h, l);
    }
}

// ---------------------------------------------------------------------------
// K1: value projection via 3xTF32 mma (round-4 version; 38.2us known-best).
// ---------------------------------------------------------------------------
__global__ void __launch_bounds__(256) k1_valproj(const float* __restrict__ x,
                                                  const float* __restrict__ vp_w,
                                                  const float* __restrict__ vp_b) {
    __shared__ unsigned Bh[4096], Bl[4096];   // [n][k] swizzled
    int t = threadIdx.x;
    for (int i = t; i < 4096; i += 256) {
        int n = i >> 6, k = i & 63;
        unsigned h, l; split_tf(vp_w[i], h, l);
        int idx = n * 64 + (k ^ SW(n));
        Bh[idx] = h; Bl[idx] = l;
    }
    __syncthreads();

    int w = t >> 5, lane = t & 31;
    int r = lane >> 2, q = lane & 3;
    size_t row0 = (size_t)blockIdx.x * 128 + w * 16;
    const float* ar = x + (row0 + r) * 64;

    float acc[8][4];
#pragma unroll
    for (int nt = 0; nt < 8; nt++)
#pragma unroll
        for (int i = 0; i < 4; i++) acc[nt][i] = 0.f;

#pragma unroll
    for (int kc = 0; kc < 8; kc++) {
        int k = kc * 8 + q;
        float a0f = __ldg(ar + k);
        float a1f = __ldg(ar + 512 + k);
        float a2f = __ldg(ar + k + 4);
        float a3f = __ldg(ar + 512 + k + 4);
        unsigned ah0, ah1, ah2, ah3, al0, al1, al2, al3;
        split_tf(a0f, ah0, al0); split_tf(a1f, ah1, al1);
        split_tf(a2f, ah2, al2); split_tf(a3f, ah3, al3);
#pragma unroll
        for (int nt = 0; nt < 8; nt++) {
            int n0 = nt * 8 + r;
            int base = n0 * 64, s = SW(n0);
            unsigned bh0 = Bh[base + (k ^ s)];
            unsigned bh1 = Bh[base + ((k + 4) ^ s)];
            unsigned bl0 = Bl[base + (k ^ s)];
            unsigned bl1 = Bl[base + ((k + 4) ^ s)];
            mma8(acc[nt], ah0, ah1, ah2, ah3, bh0, bh1);
            mma8(acc[nt], ah0, ah1, ah2, ah3, bl0, bl1);
            mma8(acc[nt], al0, al1, al2, al3, bh0, bh1);
        }
    }
#pragma unroll
    for (int nt = 0; nt < 8; nt++) {
        int jc = nt * 8 + 2 * q;
        float2 b2 = __ldg((const float2*)(vp_b + jc));
        *(float2*)&g_value[(row0 + r) * 64 + jc] =
            make_float2(acc[nt][0] + b2.x, acc[nt][1] + b2.y);
        *(float2*)&g_value[(row0 + r + 8) * 64 + jc] =
            make_float2(acc[nt][2] + b2.x, acc[nt][3] + b2.y);
    }
}

// ---------------------------------------------------------------------------
// K2: depthwise 3x3 conv (sliding window) + om GEMM via 3xTF32 mma.
// Conv output split ONCE at store into interleaved uint2 smem (hi,lo);
// B fragments loaded directly from pre-split global g_omw2 (L1-hot).
// smem = 32KB static (d_i only).
// ---------------------------------------------------------------------------
__global__ void __launch_bounds__(256) k2_dwom(const float* __restrict__ x,
                                               const float* __restrict__ dw_w,
                                               const float* __restrict__ dw_b,
                                               const float* __restrict__ om_b) {
    __shared__ uint2 d_i[4096];       // [px][c] swizzled, (hi,lo)
    int t = threadIdx.x;

    int bb = blockIdx.x >> 8;
    int p0 = (blockIdx.x & 255) * 64;
    int h = p0 >> 7;
    int w0 = p0 & 127;
    const float* xb = x + (size_t)bb * (PB * 64);

    // Phase A: conv, sliding window. thread = (channel c, pixel group pg).
    {
        int c = t & 63;
        int pg = t >> 6;
        float wk[9];
#pragma unroll
        for (int k = 0; k < 9; k++) wk[k] = dw_w[c * 9 + k];
        float bias = dw_b[c];
        int wstart = w0 + pg * 16;
        const float* xc = xb + c;
        float v[3][3];
#pragma unroll
        for (int ky = 0; ky < 3; ky++) {
            int yy = h + ky - 1;
            bool yok = (unsigned)yy < 128u;
            int xm1 = wstart - 1;
            v[ky][1] = (yok && (unsigned)xm1 < 128u)
                           ? __ldg(xc + ((size_t)((yy << 7) + xm1) << 6)) : 0.f;
            v[ky][2] = yok ? __ldg(xc + ((size_t)((yy << 7) + wstart) << 6)) : 0.f;
        }
        for (int i = 0; i < 16; i++) {
            int w = wstart + i;
            int xp1 = w + 1;
#pragma unroll
            for (int ky = 0; ky < 3; ky++) {
                int yy = h + ky - 1;
                v[ky][0] = v[ky][1];
                v[ky][1] = v[ky][2];
                v[ky][2] = ((unsigned)yy < 128u && (unsigned)xp1 < 128u)
                               ? __ldg(xc + ((size_t)((yy << 7) + xp1) << 6)) : 0.f;
            }
            float acc = bias;
#pragma unroll
            for (int ky = 0; ky < 3; ky++)
#pragma unroll
                for (int kx = 0; kx < 3; kx++)
                    acc = fmaf(v[ky][kx], wk[ky * 3 + kx], acc);
            int px = pg * 16 + i;
            unsigned hh_, ll_; split_tf(acc, hh_, ll_);
            d_i[px * 64 + (c ^ SW(px))] = make_uint2(hh_, ll_);
        }
    }
    __syncthreads();

    // Phase B: om GEMM. warp w -> n-tile w (w<7). 4 m-tiles of 16 px.
    int w = t >> 5;
    if (w < 7) {
        int lane = t & 31;
        int r = lane >> 2, q = lane & 3;
        float acc[4][4];
#pragma unroll
        for (int mt = 0; mt < 4; mt++)
#pragma unroll
            for (int i = 0; i < 4; i++) acc[mt][i] = 0.f;
        int n0 = w * 8 + r;
        int nbase = n0 * 64;
        const uint2* bw = g_omw2 + nbase;
#pragma unroll
        for (int kc = 0; kc < 8; kc++) {
            int k = kc * 8 + q;
            uint2 b0 = __ldg(bw + k);
            uint2 b1 = __ldg(bw + k + 4);
#pragma unroll
            for (int mt = 0; mt < 4; mt++) {
                int rA = mt * 16 + r, rB = rA + 8;
                uint2 a0 = d_i[rA * 64 + (k ^ SW(rA))];
                uint2 a1 = d_i[rB * 64 + (k ^ SW(rB))];
                uint2 a2 = d_i[rA * 64 + ((k + 4) ^ SW(rA))];
                uint2 a3 = d_i[rB * 64 + ((k + 4) ^ SW(rB))];
                mma8(acc[mt], a0.x, a1.x, a2.x, a3.x, b0.x, b1.x);
                mma8(acc[mt], a0.x, a1.x, a2.x, a3.x, b0.y, b1.y);
                mma8(acc[mt], a0.y, a1.y, a2.y, a3.y, b0.x, b1.x);
            }
        }
        int jc = w * 8 + 2 * q;
        if (jc < 54) {
            float2 ob2 = __ldg((const float2*)(om_b + jc));
#pragma unroll
            for (int mt = 0; mt < 4; mt++) {
                int pxA = p0 + mt * 16 + r;
                size_t baseA = ((size_t)bb * PB + pxA) * 54;
                *(float2*)&g_om[baseA + jc] =
                    make_float2(acc[mt][0] + ob2.x, acc[mt][1] + ob2.y);
                *(float2*)&g_om[baseA + 54 * 8 + jc] =
                    make_float2(acc[mt][2] + ob2.x, acc[mt][3] + ob2.y);
            }
        }
    }
}

// ---------------------------------------------------------------------------
// K3: DCN. Phase W: precomputed branch-free geometry (clamped base + 4
// pre-masked corner weights). Gather: LDS + 4x LDG.128 + 16 FFMA per tap,
// output split ONCE into interleaved uint2 smem. op GEMM: B direct from
// pre-split global g_opw2, A single LDS.64 per fragment -> pure LDS/LDG+mma.
// smem = 27.9KB static. In-register pair fold + BN + ReLU epilogue.
// ---------------------------------------------------------------------------
__global__ void __launch_bounds__(256) k3_dcn(const float* __restrict__ op_b,
                                              const float* __restrict__ bn_g,
                                              const float* __restrict__ bn_b,
                                              const float* __restrict__ bn_m,
                                              const float* __restrict__ bn_v,
                                              float* __restrict__ out) {
    __shared__ __align__(16) float4 s_w4[576];   // 9216 B
    __shared__ int s_lin[576];                   // 2304 B
    __shared__ uint2 c_i[2048];                  // 16384 B, core [pl][c] swizzled (hi,lo)
    int t = threadIdx.x;

    int bb = blockIdx.x >> 9;
    int p0 = (blockIdx.x & 511) * 16;        // in [0, 8192)

    // Phase W: 32 px x 2 g x 9 k = 576 geometry items.
    for (int it = t; it < 576; it += 256) {
        int pl = it / 18;
        int rem = it - pl * 18;
        int g = rem / 9;
        int k = rem - g * 9;
        int p = p0 + ((pl < 16) ? pl : (pl - 16 + 8192));
        int h = p >> 7, w = p & 127;
        const float* om = g_om + ((size_t)bb * PB + p) * 54 + g * 27;
        float ox = om[2 * k], oy = om[2 * k + 1], m = om[18 + k];
        float ix = (float)w + ((float)(k - (k / 3) * 3) - 1.0f + ox) * 2.0f;
        float iy = (float)h + ((float)(k / 3) - 1.0f + oy) * 2.0f;
        float xf = floorf(ix), yf = floorf(iy);
        float tx = ix - xf, ty = iy - yf;
        int x0 = (int)xf, y0 = (int)yf;
        float wx0 = ((unsigned)x0 < 128u) ? (1.f - tx) : 0.f;
        float wx1 = ((unsigned)(x0 + 1) < 128u) ? tx : 0.f;
        int x0c = x0;
        if (x0 < 0)        { wx0 = wx1; wx1 = 0.f; x0c = 0; }
        else if (x0 > 126) { wx1 = wx0; wx0 = 0.f; x0c = 126; }
        float wy0 = ((unsigned)y0 < 128u) ? (1.f - ty) : 0.f;
        float wy1 = ((unsigned)(y0 + 1) < 128u) ? ty : 0.f;
        int y0c = y0;
        if (y0 < 0)        { wy0 = wy1; wy1 = 0.f; y0c = 0; }
        else if (y0 > 126) { wy1 = wy0; wy0 = 0.f; y0c = 126; }
        s_lin[it] = (y0c << 7) + x0c;
        s_w4[it] = make_float4(wy0 * wx0 * m, wy0 * wx1 * m,
                               wy1 * wx0 * m, wy1 * wx1 * m);
    }
    __syncthreads();

    // Gather: 16 lanes per pixel (4 channels each), 2 passes over 32 px.
    {
        int sub = t & 15;
        int g = sub >> 3;
        int d0 = (sub & 7) * 4;
        int plh = t >> 4;
        int cb = g * 32 + d0;
        const float* vb = g_value + (size_t)bb * (PB * 64) + cb;
#pragma unroll
        for (int pass = 0; pass < 2; pass++) {
            int pl = plh + pass * 16;
            int ib = pl * 18 + g * 9;
            float a0 = 0.f, a1 = 0.f, a2 = 0.f, a3 = 0.f;
#pragma unroll
            for (int k = 0; k < 9; k++) {
                int lin = s_lin[ib + k];
                float4 w4 = s_w4[ib + k];
                const float* q = vb + (size_t)lin * 64;
                float4 v00 = __ldg((const float4*)(q));
                float4 v01 = __ldg((const float4*)(q + 64));
                float4 v10 = __ldg((const float4*)(q + 8192));
                float4 v11 = __ldg((const float4*)(q + 8256));
                a0 = fmaf(w4.x, v00.x, a0); a1 = fmaf(w4.x, v00.y, a1);
                a2 = fmaf(w4.x, v00.z, a2); a3 = fmaf(w4.x, v00.w, a3);
                a0 = fmaf(w4.y, v01.x, a0); a1 = fmaf(w4.y, v01.y, a1);
                a2 = fmaf(w4.y, v01.z, a2); a3 = fmaf(w4.y, v01.w, a3);
                a0 = fmaf(w4.z, v10.x, a0); a1 = fmaf(w4.z, v10.y, a1);
                a2 = fmaf(w4.z, v10.z, a2); a3 = fmaf(w4.z, v10.w, a3);
                a0 = fmaf(w4.w, v11.x, a0); a1 = fmaf(w4.w, v11.y, a1);
                a2 = fmaf(w4.w, v11.z, a2); a3 = fmaf(w4.w, v11.w, a3);
            }
            // Split once at store (removes 8x redundant split in GEMM phase).
            uint2* cp = &c_i[pl * 64 + (cb ^ SW(pl))];
            unsigned h0, l0, h1, l1, h2, l2, h3, l3;
            split_tf(a0, h0, l0); split_tf(a1, h1, l1);
            split_tf(a2, h2, l2); split_tf(a3, h3, l3);
            cp[0] = make_uint2(h0, l0);
            cp[1] = make_uint2(h1, l1);
            cp[2] = make_uint2(h2, l2);
            cp[3] = make_uint2(h3, l3);
        }
    }
    __syncthreads();

    // op GEMM via mma: warp w -> n-tile w; m-tiles rows 0-15 (A) and 16-31 (B).
    {
        int w = t >> 5, lane = t & 31;
        int r = lane >> 2, q = lane & 3;
        float accA[4] = {0.f, 0.f, 0.f, 0.f};
        float accB[4] = {0.f, 0.f, 0.f, 0.f};
        int n0 = w * 8 + r;
        const uint2* bw = g_opw2 + n0 * 64;
#pragma unroll
        for (int kc = 0; kc < 8; kc++) {
            int k = kc * 8 + q;
            uint2 b0 = __ldg(bw + k);
            uint2 b1 = __ldg(bw + k + 4);
            {
                int rA = r, rB = r + 8;
                uint2 a0 = c_i[rA * 64 + (k ^ SW(rA))];
                uint2 a1 = c_i[rB * 64 + (k ^ SW(rB))];
                uint2 a2 = c_i[rA * 64 + ((k + 4) ^ SW(rA))];
                uint2 a3 = c_i[rB * 64 + ((k + 4) ^ SW(rB))];
                mma8(accA, a0.x, a1.x, a2.x, a3.x, b0.x, b1.x);
                mma8(accA, a0.x, a1.x, a2.x, a3.x, b0.y, b1.y);
                mma8(accA, a0.y, a1.y, a2.y, a3.y, b0.x, b1.x);
            }
            {
                int rA = 16 + r, rB = 24 + r;
                uint2 a0 = c_i[rA * 64 + (k ^ SW(rA))];
                uint2 a1 = c_i[rB * 64 + (k ^ SW(rB))];
                uint2 a2 = c_i[rA * 64 + ((k + 4) ^ SW(rA))];
                uint2 a3 = c_i[rB * 64 + ((k + 4) ^ SW(rB))];
                mma8(accB, a0.x, a1.x, a2.x, a3.x, b0.x, b1.x);
                mma8(accB, a0.x, a1.x, a2.x, a3.x, b0.y, b1.y);
                mma8(accB, a0.y, a1.y, a2.y, a3.y, b0.x, b1.x);
            }
        }
        int jc = w * 8 + 2 * q;
        float2 ob2 = __ldg((const float2*)(op_b + jc));
        int cz = p0 >> 8;
        float sA = __ldg(bn_g + cz) * rsqrtf(__ldg(bn_v + cz) + 1e-5f);
        float sB = fmaf(-sA, __ldg(bn_m + cz), __ldg(bn_b + cz));
#pragma unroll
        for (int half = 0; half < 2; half++) {
            int rr = r + half * 8;
            int i0 = half * 2, i1 = half * 2 + 1;
            int p = p0 + rr;
            float z0 = fmaf(0.5f * (accA[i0] + accB[i0]) + ob2.x, sA, sB);
            float z1 = fmaf(0.5f * (accA[i1] + accB[i1]) + ob2.y, sA, sB);
            int hh = (p >> 1) & 127;
            int qq = p & 1;
            size_t base = (((size_t)bb * 32 + cz) * 128 + hh) * 128 + (qq << 6);
            *(float2*)&out[base + jc] =
                make_float2(fmaxf(z0, 0.f), fmaxf(z1, 0.f));
        }
    }
}

// ---------------------------------------------------------------------------
extern "C" void kernel_launch(void* const* d_in, const int* in_sizes, int n_in,
                              void* d_out, int out_size) {
    const float* x    = (const float*)d_in[0];
    const float* vp_w = (const float*)d_in[1];
    const float* vp_b = (const float*)d_in[2];
    const float* dw_w = (const float*)d_in[3];
    const float* dw_b = (const float*)d_in[4];
    const float* om_w = (const float*)d_in[5];
    const float* om_b = (const float*)d_in[6];
    const float* op_w = (const float*)d_in[7];
    const float* op_b = (const float*)d_in[8];
    const float* bn_g = (const float*)d_in[9];
    const float* bn_b = (const float*)d_in[10];
    const float* bn_m = (const float*)d_in[11];
    const float* bn_v = (const float*)d_in[12];
    float* out = (float*)d_out;

    k0_split<<<32, 256>>>(om_w, op_w);
    k2_dwom<<<NB * (PB / 64), 256>>>(x, dw_w, dw_b, om_b);
    k1_valproj<<<NROWS / 128, 256>>>(x, vp_w, vp_b);
    k3_dcn<<<NB * 512, 256>>>(op_b, bn_g, bn_b, bn_m, bn_v, out);
}

// round 11
// speedup vs baseline: 1.3593x; 1.0918x over previous
#include <cuda_runtime.h>
#include <cuda_fp16.h>
#include <cuda_bf16.h>

// Problem constants: B=8, C=64, H=W=128, G=2, D=32, K=9, OS=2.0
#define PB 16384
#define NB 8
#define NROWS (NB * PB)

// Value tables, fp16, group-major: [b][g][p][32ch]. A = natural pixel order
// (pair (2i,2i+1) = one 128B line). B = shifted: B[...][j][ch] = pixel j+1
// (pair (2i+1,2i+2) = one 128B line). Any horizontal corner pair -> 1 line.
__device__ __half g_valA[NB * 2 * PB * 32];
__device__ __half g_valB[NB * 2 * PB * 32];
__device__ float g_om[NB * PB * 54];      // (b,p,54)
__device__ uint4 g_omw4[1792];            // [w<7][kc][r*4+q] = {hi(k),lo(k),hi(k+4),lo(k+4)}
__device__ uint4 g_opw4[2048];            // [w<8][kc][r*4+q]

// XOR swizzle: rows stride 64 elements, swizzle k by row to decollide banks.
#define SW(r) (((r) & 7) << 2)

__device__ __forceinline__ unsigned f2tf(float f) {
    unsigned r; asm("cvt.rna.tf32.f32 %0, %1;" : "=r"(r) : "f"(f)); return r;
}
__device__ __forceinline__ void split_tf(float f, unsigned& hi, unsigned& lo) {
    hi = f2tf(f);
    lo = f2tf(f - __uint_as_float(hi));
}
__device__ __forceinline__ void mma8(float* c, unsigned a0, unsigned a1,
                                     unsigned a2, unsigned a3,
                                     unsigned b0, unsigned b1) {
    asm("mma.sync.aligned.m16n8k8.row.col.f32.tf32.tf32.f32 "
        "{%0,%1,%2,%3},{%4,%5,%6,%7},{%8,%9},{%0,%1,%2,%3};"
        : "+f"(c[0]), "+f"(c[1]), "+f"(c[2]), "+f"(c[3])
        : "r"(a0), "r"(a1), "r"(a2), "r"(a3), "r"(b0), "r"(b1));
}

// ---------------------------------------------------------------------------
// K0: pre-split om_w (padded) / op_w into fragment-ordered uint4 tables.
// One GEMM B-fragment load becomes a single coalesced LDG.128.
// ---------------------------------------------------------------------------
__global__ void __launch_bounds__(256) k0_split(const float* __restrict__ om_w,
                                                const float* __restrict__ op_w) {
    int i = blockIdx.x * 256 + threadIdx.x;
    if (i < 1792) {
        int w = i >> 8, rem = i & 255, kc = rem >> 5, rq = rem & 31;
        int r = rq >> 2, q = rq & 3;
        int n = w * 8 + r, k = kc * 8 + q;
        float f0 = (n < 54) ? om_w[n * 64 + k] : 0.f;
        float f1 = (n < 54) ? om_w[n * 64 + k + 4] : 0.f;
        uint4 v; split_tf(f0, v.x, v.y); split_tf(f1, v.z, v.w);
        g_omw4[i] = v;
    } else if (i < 3840) {
        int j = i - 1792;
        int w = j >> 8, rem = j & 255, kc = rem >> 5, rq = rem & 31;
        int r = rq >> 2, q = rq & 3;
        int n = w * 8 + r, k = kc * 8 + q;
        uint4 v; split_tf(op_w[n * 64 + k], v.x, v.y);
        split_tf(op_w[n * 64 + k + 4], v.z, v.w);
        g_opw4[j] = v;
    }
}

// ---------------------------------------------------------------------------
// K1: value projection via 3xTF32 mma (r4 core), epilogue writes fp16 A/B
// paired-corner tables instead of fp32 g_value.
// ---------------------------------------------------------------------------
__global__ void __launch_bounds__(256) k1_valproj(const float* __restrict__ x,
                                                  const float* __restrict__ vp_w,
                                                  const float* __restrict__ vp_b) {
    __shared__ unsigned Bh[4096], Bl[4096];   // [n][k] swizzled
    int t = threadIdx.x;
    for (int i = t; i < 4096; i += 256) {
        int n = i >> 6, k = i & 63;
        unsigned h, l; split_tf(vp_w[i], h, l);
        int idx = n * 64 + (k ^ SW(n));
        Bh[idx] = h; Bl[idx] = l;
    }
    __syncthreads();

    int w = t >> 5, lane = t & 31;
    int r = lane >> 2, q = lane & 3;
    size_t row0 = (size_t)blockIdx.x * 128 + w * 16;
    const float* ar = x + (row0 + r) * 64;

    float acc[8][4];
#pragma unroll
    for (int nt = 0; nt < 8; nt++)
#pragma unroll
        for (int i = 0; i < 4; i++) acc[nt][i] = 0.f;

#pragma unroll
    for (int kc = 0; kc < 8; kc++) {
        int k = kc * 8 + q;
        float a0f = __ldg(ar + k);
        float a1f = __ldg(ar + 512 + k);
        float a2f = __ldg(ar + k + 4);
        float a3f = __ldg(ar + 512 + k + 4);
        unsigned ah0, ah1, ah2, ah3, al0, al1, al2, al3;
        split_tf(a0f, ah0, al0); split_tf(a1f, ah1, al1);
        split_tf(a2f, ah2, al2); split_tf(a3f, ah3, al3);
#pragma unroll
        for (int nt = 0; nt < 8; nt++) {
            int n0 = nt * 8 + r;
            int base = n0 * 64, s = SW(n0);
            unsigned bh0 = Bh[base + (k ^ s)];
            unsigned bh1 = Bh[base + ((k + 4) ^ s)];
            unsigned bl0 = Bl[base + (k ^ s)];
            unsigned bl1 = Bl[base + ((k + 4) ^ s)];
            mma8(acc[nt], ah0, ah1, ah2, ah3, bh0, bh1);
            mma8(acc[nt], ah0, ah1, ah2, ah3, bl0, bl1);
            mma8(acc[nt], al0, al1, al2, al3, bh0, bh1);
        }
    }

    // Epilogue: write fp16 A/B tables ([b][g][p][32]).
    int pA = (int)(row0 + r);
    int b_ = pA >> 14;
    int pp = pA & 16383;
    int xA = pp & 127;
    int xB = (pp + 8) & 127;        // x of the +8 row (may wrap to next y)
    size_t gb0 = (size_t)(b_ * 2) * 16384;
#pragma unroll
    for (int nt = 0; nt < 8; nt++) {
        int jc = nt * 8 + 2 * q;
        float2 b2 = __ldg((const float2*)(vp_b + jc));
        int g = jc >> 5;
        int ch = jc & 31;
        __half2 h0 = __floats2half2_rn(acc[nt][0] + b2.x, acc[nt][1] + b2.y);
        __half2 h1 = __floats2half2_rn(acc[nt][2] + b2.x, acc[nt][3] + b2.y);
        size_t pxb = (gb0 + (size_t)g * 16384 + pp) * 32 + ch;
        *(__half2*)&g_valA[pxb] = h0;
        *(__half2*)&g_valA[pxb + 8 * 32] = h1;
        if (xA >= 1) *(__half2*)&g_valB[pxb - 32] = h0;
        if (xB >= 1) *(__half2*)&g_valB[pxb + 7 * 32] = h1;
    }
}

// ---------------------------------------------------------------------------
// K2: depthwise 3x3 conv (sliding window) + om GEMM via 3xTF32 mma.
// A pre-split at store (r10); B fragments via single LDG.128 from g_omw4.
// ---------------------------------------------------------------------------
__global__ void __launch_bounds__(256) k2_dwom(const float* __restrict__ x,
                                               const float* __restrict__ dw_w,
                                               const float* __restrict__ dw_b,
                                               const float* __restrict__ om_b) {
    __shared__ uint2 d_i[4096];       // [px][c] swizzled, (hi,lo)
    int t = threadIdx.x;

    int bb = blockIdx.x >> 8;
    int p0 = (blockIdx.x & 255) * 64;
    int h = p0 >> 7;
    int w0 = p0 & 127;
    const float* xb = x + (size_t)bb * (PB * 64);

    {
        int c = t & 63;
        int pg = t >> 6;
        float wk[9];
#pragma unroll
        for (int k = 0; k < 9; k++) wk[k] = dw_w[c * 9 + k];
        float bias = dw_b[c];
        int wstart = w0 + pg * 16;
        const float* xc = xb + c;
        float v[3][3];
#pragma unroll
        for (int ky = 0; ky < 3; ky++) {
            int yy = h + ky - 1;
            bool yok = (unsigned)yy < 128u;
            int xm1 = wstart - 1;
            v[ky][1] = (yok && (unsigned)xm1 < 128u)
                           ? __ldg(xc + ((size_t)((yy << 7) + xm1) << 6)) : 0.f;
            v[ky][2] = yok ? __ldg(xc + ((size_t)((yy << 7) + wstart) << 6)) : 0.f;
        }
        for (int i = 0; i < 16; i++) {
            int w = wstart + i;
            int xp1 = w + 1;
#pragma unroll
            for (int ky = 0; ky < 3; ky++) {
                int yy = h + ky - 1;
                v[ky][0] = v[ky][1];
                v[ky][1] = v[ky][2];
                v[ky][2] = ((unsigned)yy < 128u && (unsigned)xp1 < 128u)
                               ? __ldg(xc + ((size_t)((yy << 7) + xp1) << 6)) : 0.f;
            }
            float acc = bias;
#pragma unroll
            for (int ky = 0; ky < 3; ky++)
#pragma unroll
                for (int kx = 0; kx < 3; kx++)
                    acc = fmaf(v[ky][kx], wk[ky * 3 + kx], acc);
            int px = pg * 16 + i;
            unsigned hh_, ll_; split_tf(acc, hh_, ll_);
            d_i[px * 64 + (c ^ SW(px))] = make_uint2(hh_, ll_);
        }
    }
    __syncthreads();

    int w = t >> 5;
    if (w < 7) {
        int lane = t & 31;
        int r = lane >> 2, q = lane & 3;
        float acc[4][4];
#pragma unroll
        for (int mt = 0; mt < 4; mt++)
#pragma unroll
            for (int i = 0; i < 4; i++) acc[mt][i] = 0.f;
        const uint4* bw = g_omw4 + w * 256 + r * 4 + q;
#pragma unroll
        for (int kc = 0; kc < 8; kc++) {
            int k = kc * 8 + q;
            uint4 bv = __ldg(bw + kc * 32);
#pragma unroll
            for (int mt = 0; mt < 4; mt++) {
                int rA = mt * 16 + r, rB = rA + 8;
                uint2 a0 = d_i[rA * 64 + (k ^ SW(rA))];
                uint2 a1 = d_i[rB * 64 + (k ^ SW(rB))];
                uint2 a2 = d_i[rA * 64 + ((k + 4) ^ SW(rA))];
                uint2 a3 = d_i[rB * 64 + ((k + 4) ^ SW(rB))];
                mma8(acc[mt], a0.x, a1.x, a2.x, a3.x, bv.x, bv.z);
                mma8(acc[mt], a0.x, a1.x, a2.x, a3.x, bv.y, bv.w);
                mma8(acc[mt], a0.y, a1.y, a2.y, a3.y, bv.x, bv.z);
            }
        }
        int jc = w * 8 + 2 * q;
        if (jc < 54) {
            float2 ob2 = __ldg((const float2*)(om_b + jc));
#pragma unroll
            for (int mt = 0; mt < 4; mt++) {
                int pxA = p0 + mt * 16 + r;
                size_t baseA = ((size_t)bb * PB + pxA) * 54;
                *(float2*)&g_om[baseA + jc] =
                    make_float2(acc[mt][0] + ob2.x, acc[mt][1] + ob2.y);
                *(float2*)&g_om[baseA + 54 * 8 + jc] =
                    make_float2(acc[mt][2] + ob2.x, acc[mt][3] + ob2.y);
            }
        }
    }
}

// ---------------------------------------------------------------------------
// K3: DCN. Precomputed branch-free geometry; gather loads fp16 paired-corner
// lines (2 LDG.128 per tap per 8-lane subgroup = 2 L1 lines, vs 4 in fp32),
// fp32 accumulation, shfl fold, split once to uint2 smem. op GEMM: A LDS.64,
// B single LDG.128/kc from g_opw4. In-register pair fold + BN + ReLU.
// ---------------------------------------------------------------------------
__global__ void __launch_bounds__(256) k3_dcn(const float* __restrict__ op_b,
                                              const float* __restrict__ bn_g,
                                              const float* __restrict__ bn_b,
                                              const float* __restrict__ bn_m,
                                              const float* __restrict__ bn_v,
                                              float* __restrict__ out) {
    __shared__ __align__(16) float4 s_w4[576];   // 9216 B
    __shared__ int s_lin[576];                   // 2304 B  (packed: (pairPix<<1)|parity)
    __shared__ uint2 c_i[2048];                  // 16384 B, core [pl][c] swizzled (hi,lo)
    int t = threadIdx.x;

    int bb = blockIdx.x >> 9;
    int p0 = (blockIdx.x & 511) * 16;        // in [0, 8192)

    // Phase W: 32 px x 2 g x 9 k = 576 geometry items.
    for (int it = t; it < 576; it += 256) {
        int pl = it / 18;
        int rem = it - pl * 18;
        int g = rem / 9;
        int k = rem - g * 9;
        int p = p0 + ((pl < 16) ? pl : (pl - 16 + 8192));
        int h = p >> 7, w = p & 127;
        const float* om = g_om + ((size_t)bb * PB + p) * 54 + g * 27;
        float ox = om[2 * k], oy = om[2 * k + 1], m = om[18 + k];
        float ix = (float)w + ((float)(k - (k / 3) * 3) - 1.0f + ox) * 2.0f;
        float iy = (float)h + ((float)(k / 3) - 1.0f + oy) * 2.0f;
        float xf = floorf(ix), yf = floorf(iy);
        float tx = ix - xf, ty = iy - yf;
        int x0 = (int)xf, y0 = (int)yf;
        float wx0 = ((unsigned)x0 < 128u) ? (1.f - tx) : 0.f;
        float wx1 = ((unsigned)(x0 + 1) < 128u) ? tx : 0.f;
        int x0c = x0;
        if (x0 < 0)        { wx0 = wx1; wx1 = 0.f; x0c = 0; }
        else if (x0 > 126) { wx1 = wx0; wx0 = 0.f; x0c = 126; }
        float wy0 = ((unsigned)y0 < 128u) ? (1.f - ty) : 0.f;
        float wy1 = ((unsigned)(y0 + 1) < 128u) ? ty : 0.f;
        int y0c = y0;
        if (y0 < 0)        { wy0 = wy1; wy1 = 0.f; y0c = 0; }
        else if (y0 > 126) { wy1 = wy0; wy0 = 0.f; y0c = 126; }
        // Pair-pixel index (even start) + parity selects A/B table.
        s_lin[it] = (((y0c << 7) + (x0c & ~1)) << 1) | (x0c & 1);
        s_w4[it] = make_float4(wy0 * wx0 * m, wy0 * wx1 * m,
                               wy1 * wx0 * m, wy1 * wx1 * m);
    }
    __syncthreads();

    // Gather: 8 lanes per (pixel, group); lanes 0-3 left corner, 4-7 right.
    {
        int lane = t & 31;
        int l8 = lane & 7;
        int side = l8 >> 2;          // 0 = left corner, 1 = right corner
        int cq = l8 & 3;             // channel quarter (8 ch)
        int sg_id = t >> 3;          // 0..31 subgroups per pass
#pragma unroll
        for (int pass = 0; pass < 2; pass++) {
            int sgg = sg_id + pass * 32;     // 0..63
            int pl = sgg >> 1;
            int g = sgg & 1;
            int ib = pl * 18 + g * 9;
            const __half* tabA = g_valA + (size_t)(bb * 2 + g) * (16384 * 32);
            const __half* tabB = g_valB + (size_t)(bb * 2 + g) * (16384 * 32);
            float acc[8] = {0.f, 0.f, 0.f, 0.f, 0.f, 0.f, 0.f, 0.f};
#pragma unroll
            for (int k = 0; k < 9; k++) {
                int lp = s_lin[ib + k];
                float4 w4 = s_w4[ib + k];
                const __half* tab = (lp & 1) ? tabB : tabA;
                const __half* base = tab + (size_t)(lp >> 1) * 32 + l8 * 8;
                uint4 tv = __ldg((const uint4*)base);           // top pair line
                uint4 bv = __ldg((const uint4*)(base + 4096));  // bottom (+1 row)
                float wT = side ? w4.y : w4.x;
                float wB = side ? w4.w : w4.z;
#define GACC(u, wgt, i0) do { \
    float2 f_ = __half22float2(*reinterpret_cast<const __half2*>(&(u))); \
    acc[i0] = fmaf((wgt), f_.x, acc[i0]); \
    acc[i0 + 1] = fmaf((wgt), f_.y, acc[i0 + 1]); } while (0)
                GACC(tv.x, wT, 0); GACC(tv.y, wT, 2);
                GACC(tv.z, wT, 4); GACC(tv.w, wT, 6);
                GACC(bv.x, wB, 0); GACC(bv.y, wB, 2);
                GACC(bv.z, wB, 4); GACC(bv.w, wB, 6);
#undef GACC
            }
            // Fold left/right corner partials (lanes l and l^4 share channels).
#pragma unroll
            for (int i = 0; i < 8; i++)
                acc[i] += __shfl_xor_sync(0xFFFFFFFFu, acc[i], 4);
            if (side == 0) {
                int s = SW(pl);
                int base4 = g * 32 + cq * 8;
                int e0 = pl * 64 + (base4 ^ s);
                int e1 = pl * 64 + ((base4 + 4) ^ s);
                unsigned h0, l0, h1, l1, h2, l2, h3, l3;
                unsigned h4, l4, h5, l5, h6, l6, h7, l7;
                split_tf(acc[0], h0, l0); split_tf(acc[1], h1, l1);
                split_tf(acc[2], h2, l2); split_tf(acc[3], h3, l3);
                split_tf(acc[4], h4, l4); split_tf(acc[5], h5, l5);
                split_tf(acc[6], h6, l6); split_tf(acc[7], h7, l7);
                *(uint4*)&c_i[e0]     = make_uint4(h0, l0, h1, l1);
                *(uint4*)&c_i[e0 + 2] = make_uint4(h2, l2, h3, l3);
                *(uint4*)&c_i[e1]     = make_uint4(h4, l4, h5, l5);
                *(uint4*)&c_i[e1 + 2] = make_uint4(h6, l6, h7, l7);
            }
        }
    }
    __syncthreads();

    // op GEMM via mma: warp w -> n-tile w; m-tiles rows 0-15 (A) and 16-31 (B).
    {
        int w = t >> 5, lane = t & 31;
        int r = lane >> 2, q = lane & 3;
        float accA[4] = {0.f, 0.f, 0.f, 0.f};
        float accB[4] = {0.f, 0.f, 0.f, 0.f};
        const uint4* bw = g_opw4 + w * 256 + r * 4 + q;
#pragma unroll
        for (int kc = 0; kc < 8; kc++) {
            int k = kc * 8 + q;
            uint4 bv = __ldg(bw + kc * 32);
            {
                int rA = r, rB = r + 8;
                uint2 a0 = c_i[rA * 64 + (k ^ SW(rA))];
                uint2 a1 = c_i[rB * 64 + (k ^ SW(rB))];
                uint2 a2 = c_i[rA * 64 + ((k + 4) ^ SW(rA))];
                uint2 a3 = c_i[rB * 64 + ((k + 4) ^ SW(rB))];
                mma8(accA, a0.x, a1.x, a2.x, a3.x, bv.x, bv.z);
                mma8(accA, a0.x, a1.x, a2.x, a3.x, bv.y, bv.w);
                mma8(accA, a0.y, a1.y, a2.y, a3.y, bv.x, bv.z);
            }
            {
                int rA = 16 + r, rB = 24 + r;
                uint2 a0 = c_i[rA * 64 + (k ^ SW(rA))];
                uint2 a1 = c_i[rB * 64 + (k ^ SW(rB))];
                uint2 a2 = c_i[rA * 64 + ((k + 4) ^ SW(rA))];
                uint2 a3 = c_i[rB * 64 + ((k + 4) ^ SW(rB))];
                mma8(accB, a0.x, a1.x, a2.x, a3.x, bv.x, bv.z);
                mma8(accB, a0.x, a1.x, a2.x, a3.x, bv.y, bv.w);
                mma8(accB, a0.y, a1.y, a2.y, a3.y, bv.x, bv.z);
            }
        }
        int jc = w * 8 + 2 * q;
        float2 ob2 = __ldg((const float2*)(op_b + jc));
        int cz = p0 >> 8;
        float sA = __ldg(bn_g + cz) * rsqrtf(__ldg(bn_v + cz) + 1e-5f);
        float sB = fmaf(-sA, __ldg(bn_m + cz), __ldg(bn_b + cz));
#pragma unroll
        for (int half = 0; half < 2; half++) {
            int rr = r + half * 8;
            int i0 = half * 2, i1 = half * 2 + 1;
            int p = p0 + rr;
            float z0 = fmaf(0.5f * (accA[i0] + accB[i0]) + ob2.x, sA, sB);
            float z1 = fmaf(0.5f * (accA[i1] + accB[i1]) + ob2.y, sA, sB);
            int hh = (p >> 1) & 127;
            int qq = p & 1;
            size_t base = (((size_t)bb * 32 + cz) * 128 + hh) * 128 + (qq << 6);
            *(float2*)&out[base + jc] =
                make_float2(fmaxf(z0, 0.f), fmaxf(z1, 0.f));
        }
    }
}

// ---------------------------------------------------------------------------
extern "C" void kernel_launch(void* const* d_in, const int* in_sizes, int n_in,
                              void* d_out, int out_size) {
    const float* x    = (const float*)d_in[0];
    const float* vp_w = (const float*)d_in[1];
    const float* vp_b = (const float*)d_in[2];
    const float* dw_w = (const float*)d_in[3];
    const float* dw_b = (const float*)d_in[4];
    const float* om_w = (const float*)d_in[5];
    const float* om_b = (const float*)d_in[6];
    const float* op_w = (const float*)d_in[7];
    const float* op_b = (const float*)d_in[8];
    const float* bn_g = (const float*)d_in[9];
    const float* bn_b = (const float*)d_in[10];
    const float* bn_m = (const float*)d_in[11];
    const float* bn_v = (const float*)d_in[12];
    float* out = (float*)d_out;

    k0_split<<<15, 256>>>(om_w, op_w);
    k2_dwom<<<NB * (PB / 64), 256>>>(x, dw_w, dw_b, om_b);
    k1_valproj<<<NROWS / 128, 256>>>(x, vp_w, vp_b);
    k3_dcn<<<NB * 512, 256>>>(op_b, bn_g, bn_b, bn_m, bn_v, out);
}

// round 12
// speedup vs baseline: 1.8765x; 1.3805x over previous
#include <cuda_runtime.h>
#include <cuda_fp16.h>
#include <cuda_bf16.h>

// Problem constants: B=8, C=64, H=W=128, G=2, D=32, K=9, OS=2.0
#define PB 16384
#define NB 8
#define NROWS (NB * PB)

// Value tables, fp16, group-major: [b][g][p][32ch]. A = natural pixel order
// (pair (2i,2i+1) = one 128B line). B = shifted by one pixel.
__device__ __half g_valA[NB * 2 * PB * 32];
__device__ __half g_valB[NB * 2 * PB * 32];
__device__ float g_om[NB * PB * 54];      // (b,p,54)
// HMMA B-fragment tables: [w][kc][lane] -> {h2(W[n][k0],W[n][k0+1]), h2(W[n][k0+8],W[n][k0+9])}
// n = w*8 + (lane>>2), k0 = kc*16 + 2*(lane&3).
__device__ uint2 g_omwh[896];             // 7 n-tiles x 4 kc x 32 lanes
__device__ uint2 g_opwh[1024];            // 8 n-tiles x 4 kc x 32 lanes

#define SW(r) (((r) & 7) << 2)            // swizzle for tf32 k index (K1)
#define SW2(r) (((r) & 7) << 2)           // swizzle for half2 index (K2/K3)

__device__ __forceinline__ unsigned f2tf(float f) {
    unsigned r; asm("cvt.rna.tf32.f32 %0, %1;" : "=r"(r) : "f"(f)); return r;
}
__device__ __forceinline__ void split_tf(float f, unsigned& hi, unsigned& lo) {
    hi = f2tf(f);
    lo = f2tf(f - __uint_as_float(hi));
}
__device__ __forceinline__ void mma8(float* c, unsigned a0, unsigned a1,
                                     unsigned a2, unsigned a3,
                                     unsigned b0, unsigned b1) {
    asm("mma.sync.aligned.m16n8k8.row.col.f32.tf32.tf32.f32 "
        "{%0,%1,%2,%3},{%4,%5,%6,%7},{%8,%9},{%0,%1,%2,%3};"
        : "+f"(c[0]), "+f"(c[1]), "+f"(c[2]), "+f"(c[3])
        : "r"(a0), "r"(a1), "r"(a2), "r"(a3), "r"(b0), "r"(b1));
}
__device__ __forceinline__ void mmah(float* c, unsigned a0, unsigned a1,
                                     unsigned a2, unsigned a3,
                                     unsigned b0, unsigned b1) {
    asm("mma.sync.aligned.m16n8k16.row.col.f32.f16.f16.f32 "
        "{%0,%1,%2,%3},{%4,%5,%6,%7},{%8,%9},{%0,%1,%2,%3};"
        : "+f"(c[0]), "+f"(c[1]), "+f"(c[2]), "+f"(c[3])
        : "r"(a0), "r"(a1), "r"(a2), "r"(a3), "r"(b0), "r"(b1));
}
__device__ __forceinline__ unsigned packh2(float a, float b) {
    __half2 h = __floats2half2_rn(a, b);
    return *reinterpret_cast<unsigned*>(&h);
}

// ---------------------------------------------------------------------------
// K0: prepack om_w / op_w into HMMA B-fragment order (fp16).
// ---------------------------------------------------------------------------
__global__ void __launch_bounds__(256) k0_split(const float* __restrict__ om_w,
                                                const float* __restrict__ op_w) {
    int i = blockIdx.x * 256 + threadIdx.x;
    if (i < 896) {
        int w = i >> 7, rem = i & 127, kc = rem >> 5, lane = rem & 31;
        int n = w * 8 + (lane >> 2), k0 = kc * 16 + 2 * (lane & 3);
        float f0 = (n < 54) ? om_w[n * 64 + k0] : 0.f;
        float f1 = (n < 54) ? om_w[n * 64 + k0 + 1] : 0.f;
        float f2 = (n < 54) ? om_w[n * 64 + k0 + 8] : 0.f;
        float f3 = (n < 54) ? om_w[n * 64 + k0 + 9] : 0.f;
        g_omwh[i] = make_uint2(packh2(f0, f1), packh2(f2, f3));
    } else if (i < 1920) {
        int j = i - 896;
        int w = j >> 7, rem = j & 127, kc = rem >> 5, lane = rem & 31;
        int n = w * 8 + (lane >> 2), k0 = kc * 16 + 2 * (lane & 3);
        g_opwh[j] = make_uint2(
            packh2(op_w[n * 64 + k0], op_w[n * 64 + k0 + 1]),
            packh2(op_w[n * 64 + k0 + 8], op_w[n * 64 + k0 + 9]));
    }
}

// ---------------------------------------------------------------------------
// K1: value projection via 3xTF32 mma (r4 core), epilogue writes fp16 A/B
// paired-corner tables. (unchanged from r11)
// ---------------------------------------------------------------------------
__global__ void __launch_bounds__(256) k1_valproj(const float* __restrict__ x,
                                                  const float* __restrict__ vp_w,
                                                  const float* __restrict__ vp_b) {
    __shared__ unsigned Bh[4096], Bl[4096];   // [n][k] swizzled
    int t = threadIdx.x;
    for (int i = t; i < 4096; i += 256) {
        int n = i >> 6, k = i & 63;
        unsigned h, l; split_tf(vp_w[i], h, l);
        int idx = n * 64 + (k ^ SW(n));
        Bh[idx] = h; Bl[idx] = l;
    }
    __syncthreads();

    int w = t >> 5, lane = t & 31;
    int r = lane >> 2, q = lane & 3;
    size_t row0 = (size_t)blockIdx.x * 128 + w * 16;
    const float* ar = x + (row0 + r) * 64;

    float acc[8][4];
#pragma unroll
    for (int nt = 0; nt < 8; nt++)
#pragma unroll
        for (int i = 0; i < 4; i++) acc[nt][i] = 0.f;

#pragma unroll
    for (int kc = 0; kc < 8; kc++) {
        int k = kc * 8 + q;
        float a0f = __ldg(ar + k);
        float a1f = __ldg(ar + 512 + k);
        float a2f = __ldg(ar + k + 4);
        float a3f = __ldg(ar + 512 + k + 4);
        unsigned ah0, ah1, ah2, ah3, al0, al1, al2, al3;
        split_tf(a0f, ah0, al0); split_tf(a1f, ah1, al1);
        split_tf(a2f, ah2, al2); split_tf(a3f, ah3, al3);
#pragma unroll
        for (int nt = 0; nt < 8; nt++) {
            int n0 = nt * 8 + r;
            int base = n0 * 64, s = SW(n0);
            unsigned bh0 = Bh[base + (k ^ s)];
            unsigned bh1 = Bh[base + ((k + 4) ^ s)];
            unsigned bl0 = Bl[base + (k ^ s)];
            unsigned bl1 = Bl[base + ((k + 4) ^ s)];
            mma8(acc[nt], ah0, ah1, ah2, ah3, bh0, bh1);
            mma8(acc[nt], ah0, ah1, ah2, ah3, bl0, bl1);
            mma8(acc[nt], al0, al1, al2, al3, bh0, bh1);
        }
    }

    int pA = (int)(row0 + r);
    int b_ = pA >> 14;
    int pp = pA & 16383;
    int xA = pp & 127;
    int xB = (pp + 8) & 127;
    size_t gb0 = (size_t)(b_ * 2) * 16384;
#pragma unroll
    for (int nt = 0; nt < 8; nt++) {
        int jc = nt * 8 + 2 * q;
        float2 b2 = __ldg((const float2*)(vp_b + jc));
        int g = jc >> 5;
        int ch = jc & 31;
        __half2 h0 = __floats2half2_rn(acc[nt][0] + b2.x, acc[nt][1] + b2.y);
        __half2 h1 = __floats2half2_rn(acc[nt][2] + b2.x, acc[nt][3] + b2.y);
        size_t pxb = (gb0 + (size_t)g * 16384 + pp) * 32 + ch;
        *(__half2*)&g_valA[pxb] = h0;
        *(__half2*)&g_valA[pxb + 8 * 32] = h1;
        if (xA >= 1) *(__half2*)&g_valB[pxb - 32] = h0;
        if (xB >= 1) *(__half2*)&g_valB[pxb + 7 * 32] = h1;
    }
}

// ---------------------------------------------------------------------------
// K2: depthwise 3x3 conv (sliding window) + om GEMM via fp16 HMMA.
// Conv output stored as half directly; B fragments 1x LDG.64/k-step.
// smem = 8KB.
// ---------------------------------------------------------------------------
__global__ void __launch_bounds__(256) k2_dwom(const float* __restrict__ x,
                                               const float* __restrict__ dw_w,
                                               const float* __restrict__ dw_b,
                                               const float* __restrict__ om_b) {
    __shared__ unsigned d2[2048];     // 64 px x 32 half2, swizzled
    int t = threadIdx.x;

    int bb = blockIdx.x >> 8;
    int p0 = (blockIdx.x & 255) * 64;
    int h = p0 >> 7;
    int w0 = p0 & 127;
    const float* xb = x + (size_t)bb * (PB * 64);

    {
        int c = t & 63;
        int pg = t >> 6;
        float wk[9];
#pragma unroll
        for (int k = 0; k < 9; k++) wk[k] = dw_w[c * 9 + k];
        float bias = dw_b[c];
        int wstart = w0 + pg * 16;
        const float* xc = xb + c;
        float v[3][3];
#pragma unroll
        for (int ky = 0; ky < 3; ky++) {
            int yy = h + ky - 1;
            bool yok = (unsigned)yy < 128u;
            int xm1 = wstart - 1;
            v[ky][1] = (yok && (unsigned)xm1 < 128u)
                           ? __ldg(xc + ((size_t)((yy << 7) + xm1) << 6)) : 0.f;
            v[ky][2] = yok ? __ldg(xc + ((size_t)((yy << 7) + wstart) << 6)) : 0.f;
        }
        int c2 = c >> 1, cl = c & 1;
        for (int i = 0; i < 16; i++) {
            int w = wstart + i;
            int xp1 = w + 1;
#pragma unroll
            for (int ky = 0; ky < 3; ky++) {
                int yy = h + ky - 1;
                v[ky][0] = v[ky][1];
                v[ky][1] = v[ky][2];
                v[ky][2] = ((unsigned)yy < 128u && (unsigned)xp1 < 128u)
                               ? __ldg(xc + ((size_t)((yy << 7) + xp1) << 6)) : 0.f;
            }
            float acc = bias;
#pragma unroll
            for (int ky = 0; ky < 3; ky++)
#pragma unroll
                for (int kx = 0; kx < 3; kx++)
                    acc = fmaf(v[ky][kx], wk[ky * 3 + kx], acc);
            int px = pg * 16 + i;
            int idx = px * 32 + (c2 ^ SW2(px));
            ((__half*)d2)[idx * 2 + cl] = __float2half_rn(acc);
        }
    }
    __syncthreads();

    int w = t >> 5;
    if (w < 7) {
        int lane = t & 31;
        int r = lane >> 2, q = lane & 3;
        float acc[4][4];
#pragma unroll
        for (int mt = 0; mt < 4; mt++)
#pragma unroll
            for (int i = 0; i < 4; i++) acc[mt][i] = 0.f;
        const uint2* bw = g_omwh + w * 128 + lane;
#pragma unroll
        for (int kc = 0; kc < 4; kc++) {
            uint2 bv = __ldg(bw + kc * 32);
            int k8 = kc * 8 + q;
#pragma unroll
            for (int mt = 0; mt < 4; mt++) {
                int rA = mt * 16 + r, rB = rA + 8;
                unsigned a0 = d2[rA * 32 + (k8 ^ SW2(rA))];
                unsigned a1 = d2[rB * 32 + (k8 ^ SW2(rB))];
                unsigned a2 = d2[rA * 32 + ((k8 + 4) ^ SW2(rA))];
                unsigned a3 = d2[rB * 32 + ((k8 + 4) ^ SW2(rB))];
                mmah(acc[mt], a0, a1, a2, a3, bv.x, bv.y);
            }
        }
        int jc = w * 8 + 2 * q;
        if (jc < 54) {
            float2 ob2 = __ldg((const float2*)(om_b + jc));
#pragma unroll
            for (int mt = 0; mt < 4; mt++) {
                int pxA = p0 + mt * 16 + r;
                size_t baseA = ((size_t)bb * PB + pxA) * 54;
                *(float2*)&g_om[baseA + jc] =
                    make_float2(acc[mt][0] + ob2.x, acc[mt][1] + ob2.y);
                *(float2*)&g_om[baseA + 54 * 8 + jc] =
                    make_float2(acc[mt][2] + ob2.x, acc[mt][3] + ob2.y);
            }
        }
    }
}

// ---------------------------------------------------------------------------
// K3: DCN. Precomputed branch-free geometry; fp16 paired-corner gather with
// fp32 accumulation; core stored as half2 (no tf32 split). op GEMM via fp16
// HMMA (4 k-steps x 2 m-tiles). In-register pair fold + BN + ReLU.
// smem ~ 15.6KB.
// ---------------------------------------------------------------------------
__global__ void __launch_bounds__(256) k3_dcn(const float* __restrict__ op_b,
                                              const float* __restrict__ bn_g,
                                              const float* __restrict__ bn_b,
                                              const float* __restrict__ bn_m,
                                              const float* __restrict__ bn_v,
                                              float* __restrict__ out) {
    __shared__ __align__(16) float4 s_w4[576];   // 9216 B
    __shared__ int s_lin[576];                   // 2304 B
    __shared__ __align__(16) unsigned s_c[1024]; // 32 px x 32 half2, swizzled
    int t = threadIdx.x;

    int bb = blockIdx.x >> 9;
    int p0 = (blockIdx.x & 511) * 16;        // in [0, 8192)

    // Phase W: 32 px x 2 g x 9 k = 576 geometry items.
    for (int it = t; it < 576; it += 256) {
        int pl = it / 18;
        int rem = it - pl * 18;
        int g = rem / 9;
        int k = rem - g * 9;
        int p = p0 + ((pl < 16) ? pl : (pl - 16 + 8192));
        int h = p >> 7, w = p & 127;
        const float* om = g_om + ((size_t)bb * PB + p) * 54 + g * 27;
        float ox = om[2 * k], oy = om[2 * k + 1], m = om[18 + k];
        float ix = (float)w + ((float)(k - (k / 3) * 3) - 1.0f + ox) * 2.0f;
        float iy = (float)h + ((float)(k / 3) - 1.0f + oy) * 2.0f;
        float xf = floorf(ix), yf = floorf(iy);
        float tx = ix - xf, ty = iy - yf;
        int x0 = (int)xf, y0 = (int)yf;
        float wx0 = ((unsigned)x0 < 128u) ? (1.f - tx) : 0.f;
        float wx1 = ((unsigned)(x0 + 1) < 128u) ? tx : 0.f;
        int x0c = x0;
        if (x0 < 0)        { wx0 = wx1; wx1 = 0.f; x0c = 0; }
        else if (x0 > 126) { wx1 = wx0; wx0 = 0.f; x0c = 126; }
        float wy0 = ((unsigned)y0 < 128u) ? (1.f - ty) : 0.f;
        float wy1 = ((unsigned)(y0 + 1) < 128u) ? ty : 0.f;
        int y0c = y0;
        if (y0 < 0)        { wy0 = wy1; wy1 = 0.f; y0c = 0; }
        else if (y0 > 126) { wy1 = wy0; wy0 = 0.f; y0c = 126; }
        s_lin[it] = (((y0c << 7) + (x0c & ~1)) << 1) | (x0c & 1);
        s_w4[it] = make_float4(wy0 * wx0 * m, wy0 * wx1 * m,
                               wy1 * wx0 * m, wy1 * wx1 * m);
    }
    __syncthreads();

    // Gather: 8 lanes per (pixel, group); lanes 0-3 left corner, 4-7 right.
    {
        int lane = t & 31;
        int l8 = lane & 7;
        int side = l8 >> 2;
        int cq = l8 & 3;
        int sg_id = t >> 3;
#pragma unroll
        for (int pass = 0; pass < 2; pass++) {
            int sgg = sg_id + pass * 32;     // 0..63
            int pl = sgg >> 1;
            int g = sgg & 1;
            int ib = pl * 18 + g * 9;
            const __half* tabA = g_valA + (size_t)(bb * 2 + g) * (16384 * 32);
            const __half* tabB = g_valB + (size_t)(bb * 2 + g) * (16384 * 32);
            float acc[8] = {0.f, 0.f, 0.f, 0.f, 0.f, 0.f, 0.f, 0.f};
#pragma unroll
            for (int k = 0; k < 9; k++) {
                int lp = s_lin[ib + k];
                float4 w4 = s_w4[ib + k];
                const __half* tab = (lp & 1) ? tabB : tabA;
                const __half* base = tab + (size_t)(lp >> 1) * 32 + l8 * 8;
                uint4 tv = __ldg((const uint4*)base);
                uint4 bv = __ldg((const uint4*)(base + 4096));
                float wT = side ? w4.y : w4.x;
                float wB = side ? w4.w : w4.z;
#define GACC(u, wgt, i0) do { \
    float2 f_ = __half22float2(*reinterpret_cast<const __half2*>(&(u))); \
    acc[i0] = fmaf((wgt), f_.x, acc[i0]); \
    acc[i0 + 1] = fmaf((wgt), f_.y, acc[i0 + 1]); } while (0)
                GACC(tv.x, wT, 0); GACC(tv.y, wT, 2);
                GACC(tv.z, wT, 4); GACC(tv.w, wT, 6);
                GACC(bv.x, wB, 0); GACC(bv.y, wB, 2);
                GACC(bv.z, wB, 4); GACC(bv.w, wB, 6);
#undef GACC
            }
#pragma unroll
            for (int i = 0; i < 8; i++)
                acc[i] += __shfl_xor_sync(0xFFFFFFFFu, acc[i], 4);
            if (side == 0) {
                int c2 = g * 16 + cq * 4;
                int idx = pl * 32 + (c2 ^ SW2(pl));
                uint4 v;
                v.x = packh2(acc[0], acc[1]);
                v.y = packh2(acc[2], acc[3]);
                v.z = packh2(acc[4], acc[5]);
                v.w = packh2(acc[6], acc[7]);
                *(uint4*)&s_c[idx] = v;
            }
        }
    }
    __syncthreads();

    // op GEMM via fp16 HMMA: warp w -> n-tile w; m-tiles rows 0-15 / 16-31.
    {
        int w = t >> 5, lane = t & 31;
        int r = lane >> 2, q = lane & 3;
        float accA[4] = {0.f, 0.f, 0.f, 0.f};
        float accB[4] = {0.f, 0.f, 0.f, 0.f};
        const uint2* bw = g_opwh + w * 128 + lane;
#pragma unroll
        for (int kc = 0; kc < 4; kc++) {
            uint2 bv = __ldg(bw + kc * 32);
            int k8 = kc * 8 + q;
            {
                int rA = r, rB = r + 8;
                unsigned a0 = s_c[rA * 32 + (k8 ^ SW2(rA))];
                unsigned a1 = s_c[rB * 32 + (k8 ^ SW2(rB))];
                unsigned a2 = s_c[rA * 32 + ((k8 + 4) ^ SW2(rA))];
                unsigned a3 = s_c[rB * 32 + ((k8 + 4) ^ SW2(rB))];
                mmah(accA, a0, a1, a2, a3, bv.x, bv.y);
            }
            {
                int rA = 16 + r, rB = 24 + r;
                unsigned a0 = s_c[rA * 32 + (k8 ^ SW2(rA))];
                unsigned a1 = s_c[rB * 32 + (k8 ^ SW2(rB))];
                unsigned a2 = s_c[rA * 32 + ((k8 + 4) ^ SW2(rA))];
                unsigned a3 = s_c[rB * 32 + ((k8 + 4) ^ SW2(rB))];
                mmah(accB, a0, a1, a2, a3, bv.x, bv.y);
            }
        }
        int jc = w * 8 + 2 * q;
        float2 ob2 = __ldg((const float2*)(op_b + jc));
        int cz = p0 >> 8;
        float sA = __ldg(bn_g + cz) * rsqrtf(__ldg(bn_v + cz) + 1e-5f);
        float sB = fmaf(-sA, __ldg(bn_m + cz), __ldg(bn_b + cz));
#pragma unroll
        for (int half = 0; half < 2; half++) {
            int rr = r + half * 8;
            int i0 = half * 2, i1 = half * 2 + 1;
            int p = p0 + rr;
            float z0 = fmaf(0.5f * (accA[i0] + accB[i0]) + ob2.x, sA, sB);
            float z1 = fmaf(0.5f * (accA[i1] + accB[i1]) + ob2.y, sA, sB);
            int hh = (p >> 1) & 127;
            int qq = p & 1;
            size_t base = (((size_t)bb * 32 + cz) * 128 + hh) * 128 + (qq << 6);
            *(float2*)&out[base + jc] =
                make_float2(fmaxf(z0, 0.f), fmaxf(z1, 0.f));
        }
    }
}

// ---------------------------------------------------------------------------
extern "C" void kernel_launch(void* const* d_in, const int* in_sizes, int n_in,
                              void* d_out, int out_size) {
    const float* x    = (const float*)d_in[0];
    const float* vp_w = (const float*)d_in[1];
    const float* vp_b = (const float*)d_in[2];
    const float* dw_w = (const float*)d_in[3];
    const float* dw_b = (const float*)d_in[4];
    const float* om_w = (const float*)d_in[5];
    const float* om_b = (const float*)d_in[6];
    const float* op_w = (const float*)d_in[7];
    const float* op_b = (const float*)d_in[8];
    const float* bn_g = (const float*)d_in[9];
    const float* bn_b = (const float*)d_in[10];
    const float* bn_m = (const float*)d_in[11];
    const float* bn_v = (const float*)d_in[12];
    float* out = (float*)d_out;

    k0_split<<<8, 256>>>(om_w, op_w);
    k2_dwom<<<NB * (PB / 64), 256>>>(x, dw_w, dw_b, om_b);
    k1_valproj<<<NROWS / 128, 256>>>(x, vp_w, vp_b);
    k3_dcn<<<NB * 512, 256>>>(op_b, bn_g, bn_b, bn_m, bn_v, out);
}

// round 14
// speedup vs baseline: 2.2304x; 1.1886x over previous
#include <cuda_runtime.h>
#include <cuda_fp16.h>
#include <cuda_bf16.h>

// Problem constants: B=8, C=64, H=W=128, G=2, D=32, K=9, OS=2.0
#define PB 16384
#define NB 8
#define NROWS (NB * PB)
#define TAB (NB * 2 * PB * 32)   // element offset of the shifted (B) value table

// Merged value table, fp16, group-major: [parity][b][g][p][32ch].
// parity 0 = natural pixel pairs (pair (2i,2i+1) = one 128B line),
// parity 1 = shifted by one pixel (pair (2i+1,2i+2) = one line).
__device__ __half g_val[2 * NB * 2 * PB * 32];
__device__ float g_om[NB * PB * 54];      // (b,p,54)
// HMMA B-fragment tables (lane order: n = base + (lane>>2), k0 = kc*16 + 2*(lane&3)).
__device__ uint2 g_omwh[896];             // om: 7 n-tiles x 4 kc x 32 lanes {b0,b1}
__device__ uint2 g_opwh[1024];            // op: 8 n-tiles x 4 kc x 32 lanes
__device__ uint4 g_vpwh[1024];            // vp: 8 n-tiles x 4 kc x 32 lanes {bh0,bh1,bl0,bl1}

#define SW2(r) (((r) & 7) << 2)           // swizzle for half2 index (K2/K3)

__device__ __forceinline__ void mmah(float* c, unsigned a0, unsigned a1,
                                     unsigned a2, unsigned a3,
                                     unsigned b0, unsigned b1) {
    asm("mma.sync.aligned.m16n8k16.row.col.f32.f16.f16.f32 "
        "{%0,%1,%2,%3},{%4,%5,%6,%7},{%8,%9},{%0,%1,%2,%3};"
        : "+f"(c[0]), "+f"(c[1]), "+f"(c[2]), "+f"(c[3])
        : "r"(a0), "r"(a1), "r"(a2), "r"(a3), "r"(b0), "r"(b1));
}
__device__ __forceinline__ unsigned packh2(float a, float b) {
    __half2 h = __floats2half2_rn(a, b);
    return *reinterpret_cast<unsigned*>(&h);
}
// fp16 hi/lo split of a float pair (residual <= 2^-11 -> 3-term product is fp32-class).
__device__ __forceinline__ void split_h2(float a, float b, unsigned& hi, unsigned& lo) {
    __half2 h = __floats2half2_rn(a, b);
    float2 hf = __half22float2(h);
    __half2 l = __floats2half2_rn(a - hf.x, b - hf.y);
    hi = *reinterpret_cast<unsigned*>(&h);
    lo = *reinterpret_cast<unsigned*>(&l);
}

// ---------------------------------------------------------------------------
// K0: prepack om_w / op_w (fp16) and vp_w (fp16 hi/lo) into HMMA fragment order.
// ---------------------------------------------------------------------------
__global__ void __launch_bounds__(256) k0_split(const float* __restrict__ om_w,
                                                const float* __restrict__ op_w,
                                                const float* __restrict__ vp_w) {
    int i = blockIdx.x * 256 + threadIdx.x;
    if (i < 896) {
        int w = i >> 7, rem = i & 127, kc = rem >> 5, lane = rem & 31;
        int n = w * 8 + (lane >> 2), k0 = kc * 16 + 2 * (lane & 3);
        float f0 = (n < 54) ? om_w[n * 64 + k0] : 0.f;
        float f1 = (n < 54) ? om_w[n * 64 + k0 + 1] : 0.f;
        float f2 = (n < 54) ? om_w[n * 64 + k0 + 8] : 0.f;
        float f3 = (n < 54) ? om_w[n * 64 + k0 + 9] : 0.f;
        g_omwh[i] = make_uint2(packh2(f0, f1), packh2(f2, f3));
    } else if (i < 1920) {
        int j = i - 896;
        int w = j >> 7, rem = j & 127, kc = rem >> 5, lane = rem & 31;
        int n = w * 8 + (lane >> 2), k0 = kc * 16 + 2 * (lane & 3);
        g_opwh[j] = make_uint2(
            packh2(op_w[n * 64 + k0], op_w[n * 64 + k0 + 1]),
            packh2(op_w[n * 64 + k0 + 8], op_w[n * 64 + k0 + 9]));
    } else if (i < 2944) {
        int j = i - 1920;
        int nt = j >> 7, rem = j & 127, kc = rem >> 5, lane = rem & 31;
        int n = nt * 8 + (lane >> 2), k0 = kc * 16 + 2 * (lane & 3);
        unsigned h0, l0, h1, l1;
        split_h2(vp_w[n * 64 + k0], vp_w[n * 64 + k0 + 1], h0, l0);
        split_h2(vp_w[n * 64 + k0 + 8], vp_w[n * 64 + k0 + 9], h1, l1);
        g_vpwh[j] = make_uint4(h0, h1, l0, l1);
    }
}

// ---------------------------------------------------------------------------
// K1: value projection via 3-term fp16-split HMMA. No smem, no sync.
// A hi/lo split in registers; B fragments one LDG.128 from g_vpwh (L1-hot).
// Epilogue writes the fp16 paired-corner value tables (both parities).
// ---------------------------------------------------------------------------
__global__ void __launch_bounds__(256) k1_valproj(const float* __restrict__ x,
                                                  const float* __restrict__ vp_b) {
    int t = threadIdx.x;
    int w = t >> 5, lane = t & 31;
    int r = lane >> 2, q = lane & 3;
    size_t row0 = (size_t)blockIdx.x * 128 + w * 16;
    const float* arA = x + (row0 + r) * 64;

    float acc[8][4];
#pragma unroll
    for (int nt = 0; nt < 8; nt++)
#pragma unroll
        for (int i = 0; i < 4; i++) acc[nt][i] = 0.f;

#pragma unroll
    for (int kc = 0; kc < 4; kc++) {
        int k0 = kc * 16 + 2 * q;
        float2 fA0 = __ldg((const float2*)(arA + k0));
        float2 fB0 = __ldg((const float2*)(arA + 512 + k0));
        float2 fA1 = __ldg((const float2*)(arA + k0 + 8));
        float2 fB1 = __ldg((const float2*)(arA + 512 + k0 + 8));
        unsigned ah0, al0, ah1, al1, ah2, al2, ah3, al3;
        split_h2(fA0.x, fA0.y, ah0, al0);
        split_h2(fB0.x, fB0.y, ah1, al1);
        split_h2(fA1.x, fA1.y, ah2, al2);
        split_h2(fB1.x, fB1.y, ah3, al3);
        const uint4* bw = g_vpwh + kc * 32 + lane;
#pragma unroll
        for (int nt = 0; nt < 8; nt++) {
            uint4 bv = __ldg(bw + nt * 128);
            mmah(acc[nt], ah0, ah1, ah2, ah3, bv.x, bv.y);   // hi*hi
            mmah(acc[nt], ah0, ah1, ah2, ah3, bv.z, bv.w);   // hi*lo
            mmah(acc[nt], al0, al1, al2, al3, bv.x, bv.y);   // lo*hi
        }
    }

    int pA = (int)(row0 + r);
    int b_ = pA >> 14;
    int pp = pA & 16383;
    int xA = pp & 127;
    int xB = (pp + 8) & 127;
    size_t gb0 = (size_t)(b_ * 2) * 16384;
#pragma unroll
    for (int nt = 0; nt < 8; nt++) {
        int jc = nt * 8 + 2 * q;
        float2 b2 = __ldg((const float2*)(vp_b + jc));
        int g = jc >> 5;
        int ch = jc & 31;
        __half2 h0 = __floats2half2_rn(acc[nt][0] + b2.x, acc[nt][1] + b2.y);
        __half2 h1 = __floats2half2_rn(acc[nt][2] + b2.x, acc[nt][3] + b2.y);
        size_t pxb = (gb0 + (size_t)g * 16384 + pp) * 32 + ch;
        *(__half2*)&g_val[pxb] = h0;
        *(__half2*)&g_val[pxb + 256] = h1;                  // row +8
        if (xA >= 1) *(__half2*)&g_val[TAB + pxb - 32] = h0;
        if (xB >= 1) *(__half2*)&g_val[TAB + pxb + 224] = h1;
    }
}

// ---------------------------------------------------------------------------
// K2: depthwise 3x3 conv (sliding window) + om GEMM via fp16 HMMA.
// (r12 version, unchanged). smem = 8KB.
// ---------------------------------------------------------------------------
__global__ void __launch_bounds__(256) k2_dwom(const float* __restrict__ x,
                                               const float* __restrict__ dw_w,
                                               const float* __restrict__ dw_b,
                                               const float* __restrict__ om_b) {
    __shared__ unsigned d2[2048];     // 64 px x 32 half2, swizzled
    int t = threadIdx.x;

    int bb = blockIdx.x >> 8;
    int p0 = (blockIdx.x & 255) * 64;
    int h = p0 >> 7;
    int w0 = p0 & 127;
    const float* xb = x + (size_t)bb * (PB * 64);

    {
        int c = t & 63;
        int pg = t >> 6;
        float wk[9];
#pragma unroll
        for (int k = 0; k < 9; k++) wk[k] = dw_w[c * 9 + k];
        float bias = dw_b[c];
        int wstart = w0 + pg * 16;
        const float* xc = xb + c;
        float v[3][3];
#pragma unroll
        for (int ky = 0; ky < 3; ky++) {
            int yy = h + ky - 1;
            bool yok = (unsigned)yy < 128u;
            int xm1 = wstart - 1;
            v[ky][1] = (yok && (unsigned)xm1 < 128u)
                           ? __ldg(xc + ((size_t)((yy << 7) + xm1) << 6)) : 0.f;
            v[ky][2] = yok ? __ldg(xc + ((size_t)((yy << 7) + wstart) << 6)) : 0.f;
        }
        int c2 = c >> 1, cl = c & 1;
        for (int i = 0; i < 16; i++) {
            int w = wstart + i;
            int xp1 = w + 1;
#pragma unroll
            for (int ky = 0; ky < 3; ky++) {
                int yy = h + ky - 1;
                v[ky][0] = v[ky][1];
                v[ky][1] = v[ky][2];
                v[ky][2] = ((unsigned)yy < 128u && (unsigned)xp1 < 128u)
                               ? __ldg(xc + ((size_t)((yy << 7) + xp1) << 6)) : 0.f;
            }
            float acc = bias;
#pragma unroll
            for (int ky = 0; ky < 3; ky++)
#pragma unroll
                for (int kx = 0; kx < 3; kx++)
                    acc = fmaf(v[ky][kx], wk[ky * 3 + kx], acc);
            int px = pg * 16 + i;
            int idx = px * 32 + (c2 ^ SW2(px));
            ((__half*)d2)[idx * 2 + cl] = __float2half_rn(acc);
        }
    }
    __syncthreads();

    int w = t >> 5;
    if (w < 7) {
        int lane = t & 31;
        int r = lane >> 2, q = lane & 3;
        float acc[4][4];
#pragma unroll
        for (int mt = 0; mt < 4; mt++)
#pragma unroll
            for (int i = 0; i < 4; i++) acc[mt][i] = 0.f;
        const uint2* bw = g_omwh + w * 128 + lane;
#pragma unroll
        for (int kc = 0; kc < 4; kc++) {
            uint2 bv = __ldg(bw + kc * 32);
            int k8 = kc * 8 + q;
#pragma unroll
            for (int mt = 0; mt < 4; mt++) {
                int rA = mt * 16 + r, rB = rA + 8;
                unsigned a0 = d2[rA * 32 + (k8 ^ SW2(rA))];
                unsigned a1 = d2[rB * 32 + (k8 ^ SW2(rB))];
                unsigned a2 = d2[rA * 32 + ((k8 + 4) ^ SW2(rA))];
                unsigned a3 = d2[rB * 32 + ((k8 + 4) ^ SW2(rB))];
                mmah(acc[mt], a0, a1, a2, a3, bv.x, bv.y);
            }
        }
        int jc = w * 8 + 2 * q;
        if (jc < 54) {
            float2 ob2 = __ldg((const float2*)(om_b + jc));
#pragma unroll
            for (int mt = 0; mt < 4; mt++) {
                int pxA = p0 + mt * 16 + r;
                size_t baseA = ((size_t)bb * PB + pxA) * 54;
                *(float2*)&g_om[baseA + jc] =
                    make_float2(acc[mt][0] + ob2.x, acc[mt][1] + ob2.y);
                *(float2*)&g_om[baseA + 54 * 8 + jc] =
                    make_float2(acc[mt][2] + ob2.x, acc[mt][3] + ob2.y);
            }
        }
    }
}

// ---------------------------------------------------------------------------
// K3: DCN. Phase W precomputes the FULL gather element offset (parity-merged
// table) and per-side (top,bottom) weight pairs -> gather hot loop is
// LDS.32 + LDS.64 + 2x LDG.128 + cvt/fma, no selects, no table branching.
// op GEMM via fp16 HMMA. In-register pair fold + BN + ReLU.
// ---------------------------------------------------------------------------
__global__ void __launch_bounds__(256) k3_dcn(const float* __restrict__ op_b,
                                              const float* __restrict__ bn_g,
                                              const float* __restrict__ bn_b,
                                              const float* __restrict__ bn_m,
                                              const float* __restrict__ bn_v,
                                              float* __restrict__ out) {
    __shared__ __align__(8) float2 s_wp[1152];   // [it][side] = (wTop, wBot)
    __shared__ int s_lin[576];                   // full element offset (incl. parity)
    __shared__ __align__(16) unsigned s_c[1024]; // 32 px x 32 half2, swizzled
    int t = threadIdx.x;

    int bb = blockIdx.x >> 9;
    int p0 = (blockIdx.x & 511) * 16;        // in [0, 8192)

    // Phase W: 32 px x 2 g x 9 k = 576 geometry items.
    for (int it = t; it < 576; it += 256) {
        int pl = it / 18;
        int rem = it - pl * 18;
        int g = rem / 9;
        int k = rem - g * 9;
        int p = p0 + ((pl < 16) ? pl : (pl - 16 + 8192));
        int h = p >> 7, w = p & 127;
        const float* om = g_om + ((size_t)bb * PB + p) * 54 + g * 27;
        float ox = om[2 * k], oy = om[2 * k + 1], m = om[18 + k];
        float ix = (float)w + ((float)(k - (k / 3) * 3) - 1.0f + ox) * 2.0f;
        float iy = (float)h + ((float)(k / 3) - 1.0f + oy) * 2.0f;
        float xf = floorf(ix), yf = floorf(iy);
        float tx = ix - xf, ty = iy - yf;
        int x0 = (int)xf, y0 = (int)yf;
        float wx0 = ((unsigned)x0 < 128u) ? (1.f - tx) : 0.f;
        float wx1 = ((unsigned)(x0 + 1) < 128u) ? tx : 0.f;
        int x0c = x0;
        if (x0 < 0)        { wx0 = wx1; wx1 = 0.f; x0c = 0; }
        else if (x0 > 126) { wx1 = wx0; wx0 = 0.f; x0c = 126; }
        float wy0 = ((unsigned)y0 < 128u) ? (1.f - ty) : 0.f;
        float wy1 = ((unsigned)(y0 + 1) < 128u) ? ty : 0.f;
        int y0c = y0;
        if (y0 < 0)        { wy0 = wy1; wy1 = 0.f; y0c = 0; }
        else if (y0 > 126) { wy1 = wy0; wy0 = 0.f; y0c = 126; }
        s_lin[it] = ((x0c & 1) ? TAB : 0) + ((y0c << 7) + (x0c & ~1)) * 32;
        s_wp[it * 2 + 0] = make_float2(wy0 * wx0 * m, wy1 * wx0 * m);  // left
        s_wp[it * 2 + 1] = make_float2(wy0 * wx1 * m, wy1 * wx1 * m);  // right
    }
    __syncthreads();

    // Gather: 8 lanes per (pixel, group); lanes 0-3 left corner, 4-7 right.
    {
        int lane = t & 31;
        int l8 = lane & 7;
        int side = l8 >> 2;
        int cq = l8 & 3;
        int sg_id = t >> 3;
#pragma unroll
        for (int pass = 0; pass < 2; pass++) {
            int sgg = sg_id + pass * 32;     // 0..63
            int pl = sgg >> 1;
            int g = sgg & 1;
            int ib = pl * 18 + g * 9;
            const __half* vb = g_val + (size_t)(bb * 2 + g) * (PB * 32) + l8 * 8;
            float acc[8] = {0.f, 0.f, 0.f, 0.f, 0.f, 0.f, 0.f, 0.f};
#pragma unroll
            for (int k = 0; k < 9; k++) {
                int off = s_lin[ib + k];
                float2 wp = s_wp[(ib + k) * 2 + side];
                const __half* base = vb + off;
                uint4 tv = __ldg((const uint4*)base);
                uint4 bv = __ldg((const uint4*)(base + 4096));
#define GACC(u, wgt, i0) do { \
    float2 f_ = __half22float2(*reinterpret_cast<const __half2*>(&(u))); \
    acc[i0] = fmaf((wgt), f_.x, acc[i0]); \
    acc[i0 + 1] = fmaf((wgt), f_.y, acc[i0 + 1]); } while (0)
                GACC(tv.x, wp.x, 0); GACC(tv.y, wp.x, 2);
                GACC(tv.z, wp.x, 4); GACC(tv.w, wp.x, 6);
                GACC(bv.x, wp.y, 0); GACC(bv.y, wp.y, 2);
                GACC(bv.z, wp.y, 4); GACC(bv.w, wp.y, 6);
#undef GACC
            }
#pragma unroll
            for (int i = 0; i < 8; i++)
                acc[i] += __shfl_xor_sync(0xFFFFFFFFu, acc[i], 4);
            if (side == 0) {
                int c2 = g * 16 + cq * 4;
                int idx = pl * 32 + (c2 ^ SW2(pl));
                uint4 v;
                v.x = packh2(acc[0], acc[1]);
                v.y = packh2(acc[2], acc[3]);
                v.z = packh2(acc[4], acc[5]);
                v.w = packh2(acc[6], acc[7]);
                *(uint4*)&s_c[idx] = v;
            }
        }
    }
    __syncthreads();

    // op GEMM via fp16 HMMA: warp w -> n-tile w; m-tiles rows 0-15 / 16-31.
    {
        int w = t >> 5, lane = t & 31;
        int r = lane >> 2, q = lane & 3;
        float accA[4] = {0.f, 0.f, 0.f, 0.f};
        float accB[4] = {0.f, 0.f, 0.f, 0.f};
        const uint2* bw = g_opwh + w * 128 + lane;
#pragma unroll
        for (int kc = 0; kc < 4; kc++) {
            uint2 bv = __ldg(bw + kc * 32);
            int k8 = kc * 8 + q;
            {
                int rA = r, rB = r + 8;
                unsigned a0 = s_c[rA * 32 + (k8 ^ SW2(rA))];
                unsigned a1 = s_c[rB * 32 + (k8 ^ SW2(rB))];
                unsigned a2 = s_c[rA * 32 + ((k8 + 4) ^ SW2(rA))];
                unsigned a3 = s_c[rB * 32 + ((k8 + 4) ^ SW2(rB))];
                mmah(accA, a0, a1, a2, a3, bv.x, bv.y);
            }
            {
                int rA = 16 + r, rB = 24 + r;
                unsigned a0 = s_c[rA * 32 + (k8 ^ SW2(rA))];
                unsigned a1 = s_c[rB * 32 + (k8 ^ SW2(rB))];
                unsigned a2 = s_c[rA * 32 + ((k8 + 4) ^ SW2(rA))];
                unsigned a3 = s_c[rB * 32 + ((k8 + 4) ^ SW2(rB))];
                mmah(accB, a0, a1, a2, a3, bv.x, bv.y);
            }
        }
        int jc = w * 8 + 2 * q;
        float2 ob2 = __ldg((const float2*)(op_b + jc));
        int cz = p0 >> 8;
        float sA = __ldg(bn_g + cz) * rsqrtf(__ldg(bn_v + cz) + 1e-5f);
        float sB = fmaf(-sA, __ldg(bn_m + cz), __ldg(bn_b + cz));
#pragma unroll
        for (int half = 0; half < 2; half++) {
            int rr = r + half * 8;
            int i0 = half * 2, i1 = half * 2 + 1;
            int p = p0 + rr;
            float z0 = fmaf(0.5f * (accA[i0] + accB[i0]) + ob2.x, sA, sB);
            float z1 = fmaf(0.5f * (accA[i1] + accB[i1]) + ob2.y, sA, sB);
            int hh = (p >> 1) & 127;
            int qq = p & 1;
            size_t base = (((size_t)bb * 32 + cz) * 128 + hh) * 128 + (qq << 6);
            *(float2*)&out[base + jc] =
                make_float2(fmaxf(z0, 0.f), fmaxf(z1, 0.f));
        }
    }
}

// ---------------------------------------------------------------------------
extern "C" void kernel_launch(void* const* d_in, const int* in_sizes, int n_in,
                              void* d_out, int out_size) {
    const float* x    = (const float*)d_in[0];
    const float* vp_w = (const float*)d_in[1];
    const float* vp_b = (const float*)d_in[2];
    const float* dw_w = (const float*)d_in[3];
    const float* dw_b = (const float*)d_in[4];
    const float* om_w = (const float*)d_in[5];
    const float* om_b = (const float*)d_in[6];
    const float* op_w = (const float*)d_in[7];
    const float* op_b = (const float*)d_in[8];
    const float* bn_g = (const float*)d_in[9];
    const float* bn_b = (const float*)d_in[10];
    const float* bn_m = (const float*)d_in[11];
    const float* bn_v = (const float*)d_in[12];
    float* out = (float*)d_out;

    k0_split<<<12, 256>>>(om_w, op_w, vp_w);
    k2_dwom<<<NB * (PB / 64), 256>>>(x, dw_w, dw_b, om_b);
    k1_valproj<<<NROWS / 128, 256>>>(x, vp_b);
    k3_dcn<<<NB * 512, 256>>>(op_b, bn_g, bn_b, bn_m, bn_v, out);
}

// round 15
// speedup vs baseline: 2.2311x; 1.0003x over previous
#include <cuda_runtime.h>
#include <cuda_fp16.h>
#include <cuda_bf16.h>

// Problem constants: B=8, C=64, H=W=128, G=2, D=32, K=9, OS=2.0
#define PB 16384
#define NB 8
#define NROWS (NB * PB)
#define TAB (NB * 2 * PB * 32)   // element offset of the shifted (B) value table

// Merged value table, fp16, group-major: [parity][b][g][p][32ch].
__device__ __half g_val[2 * NB * 2 * PB * 32];
__device__ float g_om[NB * PB * 54];      // (b,p,54)
// HMMA B-fragment tables (lane order: n = base + (lane>>2), k0 = kc*16 + 2*(lane&3)).
__device__ uint2 g_omwh[896];             // om: 7 n-tiles x 4 kc x 32 lanes {b0,b1}
__device__ uint2 g_opwh[1024];            // op: 8 n-tiles x 4 kc x 32 lanes
__device__ uint4 g_vpwh[1024];            // vp: 8 n-tiles x 4 kc x 32 lanes {bh0,bh1,bl0,bl1}

#define SW2(r) (((r) & 7) << 2)           // swizzle for half2 index (K2/K3)

__device__ __forceinline__ void mmah(float* c, unsigned a0, unsigned a1,
                                     unsigned a2, unsigned a3,
                                     unsigned b0, unsigned b1) {
    asm("mma.sync.aligned.m16n8k16.row.col.f32.f16.f16.f32 "
        "{%0,%1,%2,%3},{%4,%5,%6,%7},{%8,%9},{%0,%1,%2,%3};"
        : "+f"(c[0]), "+f"(c[1]), "+f"(c[2]), "+f"(c[3])
        : "r"(a0), "r"(a1), "r"(a2), "r"(a3), "r"(b0), "r"(b1));
}
__device__ __forceinline__ unsigned packh2(float a, float b) {
    __half2 h = __floats2half2_rn(a, b);
    return *reinterpret_cast<unsigned*>(&h);
}
__device__ __forceinline__ __half2 u2h(unsigned u) {
    return *reinterpret_cast<__half2*>(&u);
}
// fp16 hi/lo split of a float pair (residual <= 2^-11 -> 3-term product is fp32-class).
__device__ __forceinline__ void split_h2(float a, float b, unsigned& hi, unsigned& lo) {
    __half2 h = __floats2half2_rn(a, b);
    float2 hf = __half22float2(h);
    __half2 l = __floats2half2_rn(a - hf.x, b - hf.y);
    hi = *reinterpret_cast<unsigned*>(&h);
    lo = *reinterpret_cast<unsigned*>(&l);
}

// ---------------------------------------------------------------------------
// K0: prepack om_w / op_w (fp16) and vp_w (fp16 hi/lo) into HMMA fragment order.
// ---------------------------------------------------------------------------
__global__ void __launch_bounds__(256) k0_split(const float* __restrict__ om_w,
                                                const float* __restrict__ op_w,
                                                const float* __restrict__ vp_w) {
    int i = blockIdx.x * 256 + threadIdx.x;
    if (i < 896) {
        int w = i >> 7, rem = i & 127, kc = rem >> 5, lane = rem & 31;
        int n = w * 8 + (lane >> 2), k0 = kc * 16 + 2 * (lane & 3);
        float f0 = (n < 54) ? om_w[n * 64 + k0] : 0.f;
        float f1 = (n < 54) ? om_w[n * 64 + k0 + 1] : 0.f;
        float f2 = (n < 54) ? om_w[n * 64 + k0 + 8] : 0.f;
        float f3 = (n < 54) ? om_w[n * 64 + k0 + 9] : 0.f;
        g_omwh[i] = make_uint2(packh2(f0, f1), packh2(f2, f3));
    } else if (i < 1920) {
        int j = i - 896;
        int w = j >> 7, rem = j & 127, kc = rem >> 5, lane = rem & 31;
        int n = w * 8 + (lane >> 2), k0 = kc * 16 + 2 * (lane & 3);
        g_opwh[j] = make_uint2(
            packh2(op_w[n * 64 + k0], op_w[n * 64 + k0 + 1]),
            packh2(op_w[n * 64 + k0 + 8], op_w[n * 64 + k0 + 9]));
    } else if (i < 2944) {
        int j = i - 1920;
        int nt = j >> 7, rem = j & 127, kc = rem >> 5, lane = rem & 31;
        int n = nt * 8 + (lane >> 2), k0 = kc * 16 + 2 * (lane & 3);
        unsigned h0, l0, h1, l1;
        split_h2(vp_w[n * 64 + k0], vp_w[n * 64 + k0 + 1], h0, l0);
        split_h2(vp_w[n * 64 + k0 + 8], vp_w[n * 64 + k0 + 9], h1, l1);
        g_vpwh[j] = make_uint4(h0, h1, l0, l1);
    }
}

// ---------------------------------------------------------------------------
// K1: value projection via 3-term fp16-split HMMA. No smem, no sync.
// (r14 version, unchanged)
// ---------------------------------------------------------------------------
__global__ void __launch_bounds__(256) k1_valproj(const float* __restrict__ x,
                                                  const float* __restrict__ vp_b) {
    int t = threadIdx.x;
    int w = t >> 5, lane = t & 31;
    int r = lane >> 2, q = lane & 3;
    size_t row0 = (size_t)blockIdx.x * 128 + w * 16;
    const float* arA = x + (row0 + r) * 64;

    float acc[8][4];
#pragma unroll
    for (int nt = 0; nt < 8; nt++)
#pragma unroll
        for (int i = 0; i < 4; i++) acc[nt][i] = 0.f;

#pragma unroll
    for (int kc = 0; kc < 4; kc++) {
        int k0 = kc * 16 + 2 * q;
        float2 fA0 = __ldg((const float2*)(arA + k0));
        float2 fB0 = __ldg((const float2*)(arA + 512 + k0));
        float2 fA1 = __ldg((const float2*)(arA + k0 + 8));
        float2 fB1 = __ldg((const float2*)(arA + 512 + k0 + 8));
        unsigned ah0, al0, ah1, al1, ah2, al2, ah3, al3;
        split_h2(fA0.x, fA0.y, ah0, al0);
        split_h2(fB0.x, fB0.y, ah1, al1);
        split_h2(fA1.x, fA1.y, ah2, al2);
        split_h2(fB1.x, fB1.y, ah3, al3);
        const uint4* bw = g_vpwh + kc * 32 + lane;
#pragma unroll
        for (int nt = 0; nt < 8; nt++) {
            uint4 bv = __ldg(bw + nt * 128);
            mmah(acc[nt], ah0, ah1, ah2, ah3, bv.x, bv.y);   // hi*hi
            mmah(acc[nt], ah0, ah1, ah2, ah3, bv.z, bv.w);   // hi*lo
            mmah(acc[nt], al0, al1, al2, al3, bv.x, bv.y);   // lo*hi
        }
    }

    int pA = (int)(row0 + r);
    int b_ = pA >> 14;
    int pp = pA & 16383;
    int xA = pp & 127;
    int xB = (pp + 8) & 127;
    size_t gb0 = (size_t)(b_ * 2) * 16384;
#pragma unroll
    for (int nt = 0; nt < 8; nt++) {
        int jc = nt * 8 + 2 * q;
        float2 b2 = __ldg((const float2*)(vp_b + jc));
        int g = jc >> 5;
        int ch = jc & 31;
        __half2 h0 = __floats2half2_rn(acc[nt][0] + b2.x, acc[nt][1] + b2.y);
        __half2 h1 = __floats2half2_rn(acc[nt][2] + b2.x, acc[nt][3] + b2.y);
        size_t pxb = (gb0 + (size_t)g * 16384 + pp) * 32 + ch;
        *(__half2*)&g_val[pxb] = h0;
        *(__half2*)&g_val[pxb + 256] = h1;                  // row +8
        if (xA >= 1) *(__half2*)&g_val[TAB + pxb - 32] = h0;
        if (xB >= 1) *(__half2*)&g_val[TAB + pxb + 224] = h1;
    }
}

// ---------------------------------------------------------------------------
// K2: depthwise 3x3 conv (sliding window) + om GEMM via fp16 HMMA.
// (r12/r14 version, unchanged). smem = 8KB.
// ---------------------------------------------------------------------------
__global__ void __launch_bounds__(256) k2_dwom(const float* __restrict__ x,
                                               const float* __restrict__ dw_w,
                                               const float* __restrict__ dw_b,
                                               const float* __restrict__ om_b) {
    __shared__ unsigned d2[2048];     // 64 px x 32 half2, swizzled
    int t = threadIdx.x;

    int bb = blockIdx.x >> 8;
    int p0 = (blockIdx.x & 255) * 64;
    int h = p0 >> 7;
    int w0 = p0 & 127;
    const float* xb = x + (size_t)bb * (PB * 64);

    {
        int c = t & 63;
        int pg = t >> 6;
        float wk[9];
#pragma unroll
        for (int k = 0; k < 9; k++) wk[k] = dw_w[c * 9 + k];
        float bias = dw_b[c];
        int wstart = w0 + pg * 16;
        const float* xc = xb + c;
        float v[3][3];
#pragma unroll
        for (int ky = 0; ky < 3; ky++) {
            int yy = h + ky - 1;
            bool yok = (unsigned)yy < 128u;
            int xm1 = wstart - 1;
            v[ky][1] = (yok && (unsigned)xm1 < 128u)
                           ? __ldg(xc + ((size_t)((yy << 7) + xm1) << 6)) : 0.f;
            v[ky][2] = yok ? __ldg(xc + ((size_t)((yy << 7) + wstart) << 6)) : 0.f;
        }
        int c2 = c >> 1, cl = c & 1;
        for (int i = 0; i < 16; i++) {
            int w = wstart + i;
            int xp1 = w + 1;
#pragma unroll
            for (int ky = 0; ky < 3; ky++) {
                int yy = h + ky - 1;
                v[ky][0] = v[ky][1];
                v[ky][1] = v[ky][2];
                v[ky][2] = ((unsigned)yy < 128u && (unsigned)xp1 < 128u)
                               ? __ldg(xc + ((size_t)((yy << 7) + xp1) << 6)) : 0.f;
            }
            float acc = bias;
#pragma unroll
            for (int ky = 0; ky < 3; ky++)
#pragma unroll
                for (int kx = 0; kx < 3; kx++)
                    acc = fmaf(v[ky][kx], wk[ky * 3 + kx], acc);
            int px = pg * 16 + i;
            int idx = px * 32 + (c2 ^ SW2(px));
            ((__half*)d2)[idx * 2 + cl] = __float2half_rn(acc);
        }
    }
    __syncthreads();

    int w = t >> 5;
    if (w < 7) {
        int lane = t & 31;
        int r = lane >> 2, q = lane & 3;
        float acc[4][4];
#pragma unroll
        for (int mt = 0; mt < 4; mt++)
#pragma unroll
            for (int i = 0; i < 4; i++) acc[mt][i] = 0.f;
        const uint2* bw = g_omwh + w * 128 + lane;
#pragma unroll
        for (int kc = 0; kc < 4; kc++) {
            uint2 bv = __ldg(bw + kc * 32);
            int k8 = kc * 8 + q;
#pragma unroll
            for (int mt = 0; mt < 4; mt++) {
                int rA = mt * 16 + r, rB = rA + 8;
                unsigned a0 = d2[rA * 32 + (k8 ^ SW2(rA))];
                unsigned a1 = d2[rB * 32 + (k8 ^ SW2(rB))];
                unsigned a2 = d2[rA * 32 + ((k8 + 4) ^ SW2(rA))];
                unsigned a3 = d2[rB * 32 + ((k8 + 4) ^ SW2(rB))];
                mmah(acc[mt], a0, a1, a2, a3, bv.x, bv.y);
            }
        }
        int jc = w * 8 + 2 * q;
        if (jc < 54) {
            float2 ob2 = __ldg((const float2*)(om_b + jc));
#pragma unroll
            for (int mt = 0; mt < 4; mt++) {
                int pxA = p0 + mt * 16 + r;
                size_t baseA = ((size_t)bb * PB + pxA) * 54;
                *(float2*)&g_om[baseA + jc] =
                    make_float2(acc[mt][0] + ob2.x, acc[mt][1] + ob2.y);
                *(float2*)&g_om[baseA + 54 * 8 + jc] =
                    make_float2(acc[mt][2] + ob2.x, acc[mt][3] + ob2.y);
            }
        }
    }
}

// ---------------------------------------------------------------------------
// K3: DCN. Gather now accumulates tap-PAIRS in packed fp16 (hfma2) and folds
// each pair-partial into f32 once (bounded rounding depth: 4 fused roundings
// per pair). Weights prestored as broadcast half2 pairs. Geometry/GEMM as r14.
// ---------------------------------------------------------------------------
__global__ void __launch_bounds__(256) k3_dcn(const float* __restrict__ op_b,
                                              const float* __restrict__ bn_g,
                                              const float* __restrict__ bn_b,
                                              const float* __restrict__ bn_m,
                                              const float* __restrict__ bn_v,
                                              float* __restrict__ out) {
    __shared__ __align__(8) uint2 s_wph[1152];   // [it][side] = {h2(wT,wT), h2(wB,wB)}
    __shared__ int s_lin[576];                   // full element offset (incl. parity)
    __shared__ __align__(16) unsigned s_c[1024]; // 32 px x 32 half2, swizzled
    int t = threadIdx.x;

    int bb = blockIdx.x >> 9;
    int p0 = (blockIdx.x & 511) * 16;        // in [0, 8192)

    // Phase W: 32 px x 2 g x 9 k = 576 geometry items.
    for (int it = t; it < 576; it += 256) {
        int pl = it / 18;
        int rem = it - pl * 18;
        int g = rem / 9;
        int k = rem - g * 9;
        int p = p0 + ((pl < 16) ? pl : (pl - 16 + 8192));
        int h = p >> 7, w = p & 127;
        const float* om = g_om + ((size_t)bb * PB + p) * 54 + g * 27;
        float ox = om[2 * k], oy = om[2 * k + 1], m = om[18 + k];
        float ix = (float)w + ((float)(k - (k / 3) * 3) - 1.0f + ox) * 2.0f;
        float iy = (float)h + ((float)(k / 3) - 1.0f + oy) * 2.0f;
        float xf = floorf(ix), yf = floorf(iy);
        float tx = ix - xf, ty = iy - yf;
        int x0 = (int)xf, y0 = (int)yf;
        float wx0 = ((unsigned)x0 < 128u) ? (1.f - tx) : 0.f;
        float wx1 = ((unsigned)(x0 + 1) < 128u) ? tx : 0.f;
        int x0c = x0;
        if (x0 < 0)        { wx0 = wx1; wx1 = 0.f; x0c = 0; }
        else if (x0 > 126) { wx1 = wx0; wx0 = 0.f; x0c = 126; }
        float wy0 = ((unsigned)y0 < 128u) ? (1.f - ty) : 0.f;
        float wy1 = ((unsigned)(y0 + 1) < 128u) ? ty : 0.f;
        int y0c = y0;
        if (y0 < 0)        { wy0 = wy1; wy1 = 0.f; y0c = 0; }
        else if (y0 > 126) { wy1 = wy0; wy0 = 0.f; y0c = 126; }
        s_lin[it] = ((x0c & 1) ? TAB : 0) + ((y0c << 7) + (x0c & ~1)) * 32;
        float wTL = wy0 * wx0 * m, wBL = wy1 * wx0 * m;
        float wTR = wy0 * wx1 * m, wBR = wy1 * wx1 * m;
        s_wph[it * 2 + 0] = make_uint2(packh2(wTL, wTL), packh2(wBL, wBL));  // left
        s_wph[it * 2 + 1] = make_uint2(packh2(wTR, wTR), packh2(wBR, wBR));  // right
    }
    __syncthreads();

    // Gather: 8 lanes per (pixel, group); lanes 0-3 left corner, 4-7 right.
    {
        int lane = t & 31;
        int l8 = lane & 7;
        int side = l8 >> 2;
        int cq = l8 & 3;
        int sg_id = t >> 3;
#pragma unroll
        for (int pass = 0; pass < 2; pass++) {
            int sgg = sg_id + pass * 32;     // 0..63
            int pl = sgg >> 1;
            int g = sgg & 1;
            int ib = pl * 18 + g * 9;
            const __half* vb = g_val + (size_t)(bb * 2 + g) * (PB * 32) + l8 * 8;
            float acc[8] = {0.f, 0.f, 0.f, 0.f, 0.f, 0.f, 0.f, 0.f};

            // 4 tap-pairs accumulated in packed fp16, folded to f32 per pair.
#pragma unroll
            for (int kp = 0; kp < 4; kp++) {
                int kA = kp * 2, kB = kp * 2 + 1;
                int offA = s_lin[ib + kA];
                int offB = s_lin[ib + kB];
                uint2 wpA = s_wph[(ib + kA) * 2 + side];
                uint2 wpB = s_wph[(ib + kB) * 2 + side];
                const __half* baA = vb + offA;
                const __half* baB = vb + offB;
                uint4 tA = __ldg((const uint4*)baA);
                uint4 bA = __ldg((const uint4*)(baA + 4096));
                uint4 tB = __ldg((const uint4*)baB);
                uint4 bB = __ldg((const uint4*)(baB + 4096));
                __half2 wTA = u2h(wpA.x), wBA = u2h(wpA.y);
                __half2 wTB = u2h(wpB.x), wBB = u2h(wpB.y);
#define PAIRACC(ua, ub, uc, ud, i0) do { \
    __half2 hh = __hmul2(u2h(ua), wTA); \
    hh = __hfma2(u2h(ub), wBA, hh); \
    hh = __hfma2(u2h(uc), wTB, hh); \
    hh = __hfma2(u2h(ud), wBB, hh); \
    float2 ff = __half22float2(hh); \
    acc[i0] += ff.x; acc[i0 + 1] += ff.y; } while (0)
                PAIRACC(tA.x, bA.x, tB.x, bB.x, 0);
                PAIRACC(tA.y, bA.y, tB.y, bB.y, 2);
                PAIRACC(tA.z, bA.z, tB.z, bB.z, 4);
                PAIRACC(tA.w, bA.w, tB.w, bB.w, 6);
#undef PAIRACC
            }
            // Singleton tap 8.
            {
                int off = s_lin[ib + 8];
                uint2 wp = s_wph[(ib + 8) * 2 + side];
                const __half* base = vb + off;
                uint4 tv = __ldg((const uint4*)base);
                uint4 bv = __ldg((const uint4*)(base + 4096));
                __half2 wT = u2h(wp.x), wB = u2h(wp.y);
#define ONEACC(ua, ub, i0) do { \
    __half2 hh = __hmul2(u2h(ua), wT); \
    hh = __hfma2(u2h(ub), wB, hh); \
    float2 ff = __half22float2(hh); \
    acc[i0] += ff.x; acc[i0 + 1] += ff.y; } while (0)
                ONEACC(tv.x, bv.x, 0);
                ONEACC(tv.y, bv.y, 2);
                ONEACC(tv.z, bv.z, 4);
                ONEACC(tv.w, bv.w, 6);
#undef ONEACC
            }
#pragma unroll
            for (int i = 0; i < 8; i++)
                acc[i] += __shfl_xor_sync(0xFFFFFFFFu, acc[i], 4);
            if (side == 0) {
                int c2 = g * 16 + cq * 4;
                int idx = pl * 32 + (c2 ^ SW2(pl));
                uint4 v;
                v.x = packh2(acc[0], acc[1]);
                v.y = packh2(acc[2], acc[3]);
                v.z = packh2(acc[4], acc[5]);
                v.w = packh2(acc[6], acc[7]);
                *(uint4*)&s_c[idx] = v;
            }
        }
    }
    __syncthreads();

    // op GEMM via fp16 HMMA: warp w -> n-tile w; m-tiles rows 0-15 / 16-31.
    {
        int w = t >> 5, lane = t & 31;
        int r = lane >> 2, q = lane & 3;
        float accA[4] = {0.f, 0.f, 0.f, 0.f};
        float accB[4] = {0.f, 0.f, 0.f, 0.f};
        const uint2* bw = g_opwh + w * 128 + lane;
#pragma unroll
        for (int kc = 0; kc < 4; kc++) {
            uint2 bv = __ldg(bw + kc * 32);
            int k8 = kc * 8 + q;
            {
                int rA = r, rB = r + 8;
                unsigned a0 = s_c[rA * 32 + (k8 ^ SW2(rA))];
                unsigned a1 = s_c[rB * 32 + (k8 ^ SW2(rB))];
                unsigned a2 = s_c[rA * 32 + ((k8 + 4) ^ SW2(rA))];
                unsigned a3 = s_c[rB * 32 + ((k8 + 4) ^ SW2(rB))];
                mmah(accA, a0, a1, a2, a3, bv.x, bv.y);
            }
            {
                int rA = 16 + r, rB = 24 + r;
                unsigned a0 = s_c[rA * 32 + (k8 ^ SW2(rA))];
                unsigned a1 = s_c[rB * 32 + (k8 ^ SW2(rB))];
                unsigned a2 = s_c[rA * 32 + ((k8 + 4) ^ SW2(rA))];
                unsigned a3 = s_c[rB * 32 + ((k8 + 4) ^ SW2(rB))];
                mmah(accB, a0, a1, a2, a3, bv.x, bv.y);
            }
        }
        int jc = w * 8 + 2 * q;
        float2 ob2 = __ldg((const float2*)(op_b + jc));
        int cz = p0 >> 8;
        float sA = __ldg(bn_g + cz) * rsqrtf(__ldg(bn_v + cz) + 1e-5f);
        float sB = fmaf(-sA, __ldg(bn_m + cz), __ldg(bn_b + cz));
#pragma unroll
        for (int half = 0; half < 2; half++) {
            int rr = r + half * 8;
            int i0 = half * 2, i1 = half * 2 + 1;
            int p = p0 + rr;
            float z0 = fmaf(0.5f * (accA[i0] + accB[i0]) + ob2.x, sA, sB);
            float z1 = fmaf(0.5f * (accA[i1] + accB[i1]) + ob2.y, sA, sB);
            int hh = (p >> 1) & 127;
            int qq = p & 1;
            size_t base = (((size_t)bb * 32 + cz) * 128 + hh) * 128 + (qq << 6);
            *(float2*)&out[base + jc] =
                make_float2(fmaxf(z0, 0.f), fmaxf(z1, 0.f));
        }
    }
}

// ---------------------------------------------------------------------------
extern "C" void kernel_launch(void* const* d_in, const int* in_sizes, int n_in,
                              void* d_out, int out_size) {
    const float* x    = (const float*)d_in[0];
    const float* vp_w = (const float*)d_in[1];
    const float* vp_b = (const float*)d_in[2];
    const float* dw_w = (const float*)d_in[3];
    const float* dw_b = (const float*)d_in[4];
    const float* om_w = (const float*)d_in[5];
    const float* om_b = (const float*)d_in[6];
    const float* op_w = (const float*)d_in[7];
    const float* op_b = (const float*)d_in[8];
    const float* bn_g = (const float*)d_in[9];
    const float* bn_b = (const float*)d_in[10];
    const float* bn_m = (const float*)d_in[11];
    const float* bn_v = (const float*)d_in[12];
    float* out = (float*)d_out;

    k0_split<<<12, 256>>>(om_w, op_w, vp_w);
    k2_dwom<<<NB * (PB / 64), 256>>>(x, dw_w, dw_b, om_b);
    k1_valproj<<<NROWS / 128, 256>>>(x, vp_b);
    k3_dcn<<<NB * 512, 256>>>(op_b, bn_g, bn_b, bn_m, bn_v, out);
}